// round 1
// baseline (speedup 1.0000x reference)
#include <cuda_runtime.h>
#include <math.h>
#include <stdint.h>

// ---------------- constants ----------------
#define kS   1024
#define kD   2048
#define kH   32
#define kHD  64
#define kF   8192
#define kNE  4
#define kVOC 50257

// ---------------- scratch (__device__ globals; allocation-free) ----------------
__device__ float g_x0 [kS*kD];
__device__ float g_q  [kS*kD];
__device__ float g_k  [kS*kD];
__device__ float g_v  [kS*kD];
__device__ float g_o  [kS*kD];
__device__ float g_p  [kS*kD];
__device__ float g_x1 [kS*kD];
__device__ float g_xn1[kS*kD];
__device__ float g_h1 [kS*kF];
__device__ float g_h3 [kS*kF];
__device__ float g_moe[kS*kD];
__device__ float g_x2 [kS*kD];
__device__ float g_x3 [kS*kD];
__device__ float g_x4 [kS*kD];
__device__ float g_wdense[kS*kNE];
__device__ float g_var[kS];

// ---------------- embed ----------------
__global__ void embed_kernel(const int* __restrict__ tok, const float* __restrict__ emb,
                             float* __restrict__ X) {
    int i = blockIdx.x * blockDim.x + threadIdx.x;   // [0, kS*kD)
    int t = i >> 11;
    int d = i & 2047;
    X[i] = emb[(size_t)tok[t] * kD + d];
}

// ---------------- RoPE (in-place) ----------------
__global__ void rope_kernel(float* __restrict__ X) {
    int i = blockIdx.x * blockDim.x + threadIdx.x;   // [0, kS*kH*32)
    int p = i & 31;
    int h = (i >> 5) & 31;
    int t = i >> 10;
    float inv = 1.0f / powf(10000.0f, (float)(2 * p) / 64.0f);
    float ang = (float)t * inv;
    float c = cosf(ang), s = sinf(ang);
    size_t base = (size_t)t * kD + h * kHD + 2 * p;
    float x0 = X[base], x1 = X[base + 1];
    X[base]     = x0 * c - x1 * s;
    X[base + 1] = x0 * s + x1 * c;
}

// ---------------- generic NT SGEMM: C[m,n] = (beta?C:0) + sc[m] * sum_k A[m,k]B[n,k] ----------------
__global__ void gemm_nt(const float* __restrict__ A, const float* __restrict__ B,
                        float* __restrict__ C, int M, int N, int K,
                        const float* __restrict__ rowScale, int rsStride, int beta) {
    __shared__ float As[16][68];
    __shared__ float Bs[16][68];
    int bm = blockIdx.y * 64, bn = blockIdx.x * 64;
    int tid = threadIdx.x;
    int tx = tid & 15, ty = tid >> 4;
    int lr = tid >> 2;
    int lk = (tid & 3) << 2;
    float acc[4][4] = {};
    for (int k0 = 0; k0 < K; k0 += 16) {
        float4 a4 = make_float4(0.f, 0.f, 0.f, 0.f);
        float4 b4 = make_float4(0.f, 0.f, 0.f, 0.f);
        int ar = bm + lr;
        int br = bn + lr;
        if (ar < M) a4 = *(const float4*)(A + (size_t)ar * K + k0 + lk);
        if (br < N) b4 = *(const float4*)(B + (size_t)br * K + k0 + lk);
        As[lk + 0][lr] = a4.x; As[lk + 1][lr] = a4.y; As[lk + 2][lr] = a4.z; As[lk + 3][lr] = a4.w;
        Bs[lk + 0][lr] = b4.x; Bs[lk + 1][lr] = b4.y; Bs[lk + 2][lr] = b4.z; Bs[lk + 3][lr] = b4.w;
        __syncthreads();
#pragma unroll
        for (int kk = 0; kk < 16; kk++) {
            float4 a = *(const float4*)&As[kk][ty << 2];
            float4 b = *(const float4*)&Bs[kk][tx << 2];
            float av[4] = {a.x, a.y, a.z, a.w};
            float bv[4] = {b.x, b.y, b.z, b.w};
#pragma unroll
            for (int i = 0; i < 4; i++)
#pragma unroll
                for (int j = 0; j < 4; j++) acc[i][j] += av[i] * bv[j];
        }
        __syncthreads();
    }
#pragma unroll
    for (int i = 0; i < 4; i++) {
        int m = bm + ty * 4 + i;
        if (m >= M) continue;
        float sc = rowScale ? rowScale[(size_t)m * rsStride] : 1.0f;
#pragma unroll
        for (int j = 0; j < 4; j++) {
            int n = bn + tx * 4 + j;
            if (n >= N) continue;
            size_t idx = (size_t)m * N + n;
            float v = acc[i][j] * sc;
            if (beta) v += C[idx];
            C[idx] = v;
        }
    }
}

// ---------------- attention: per (q-block, head), reproduces per-j-block-max exp ----------------
// smem: Qt[64][68] (d-major), KP[64][68] (K d-major, then reused as P[k][q]), Vs[64][68], den[64]
__global__ void attn_kernel(const float* __restrict__ Q, const float* __restrict__ K,
                            const float* __restrict__ V, float* __restrict__ O) {
    extern __shared__ float sm[];
    const int LD = 68;
    float* Qt  = sm;
    float* KP  = Qt + 64 * LD;
    float* Vs  = KP + 64 * LD;
    float* den = Vs + 64 * LD;
    int qi = blockIdx.x;          // query block 0..15
    int h  = blockIdx.y;          // head 0..31
    int tid = threadIdx.x;        // 256
    int tx = tid & 15, ty = tid >> 4;

    // load Q block transposed: Qt[d][q]
    for (int it = tid; it < 1024; it += 256) {
        int q = it >> 4;
        int d4 = (it & 15) << 2;
        float4 vq = *(const float4*)(Q + (size_t)(qi * 64 + q) * kD + h * kHD + d4);
        Qt[(d4 + 0) * LD + q] = vq.x;
        Qt[(d4 + 1) * LD + q] = vq.y;
        Qt[(d4 + 2) * LD + q] = vq.z;
        Qt[(d4 + 3) * LD + q] = vq.w;
    }
    if (tid < 64) den[tid] = 0.0f;

    float o[4][4] = {};
    for (int j = 0; j <= qi; j++) {
        __syncthreads();   // previous iteration's P/Vs reads done
        for (int it = tid; it < 1024; it += 256) {
            int r = it >> 4;
            int d4 = (it & 15) << 2;
            float4 kv = *(const float4*)(K + (size_t)(j * 64 + r) * kD + h * kHD + d4);
            KP[(d4 + 0) * LD + r] = kv.x;
            KP[(d4 + 1) * LD + r] = kv.y;
            KP[(d4 + 2) * LD + r] = kv.z;
            KP[(d4 + 3) * LD + r] = kv.w;
            float4 vv = *(const float4*)(V + (size_t)(j * 64 + r) * kD + h * kHD + d4);
            *(float4*)&Vs[r * LD + d4] = vv;
        }
        __syncthreads();
        // scores s[q][k] = sum_d Qt[d][q]*KP(as Kt)[d][k]
        float s[4][4] = {};
#pragma unroll 8
        for (int d = 0; d < 64; d++) {
            float4 a = *(const float4*)&Qt[d * LD + (ty << 2)];
            float4 b = *(const float4*)&KP[d * LD + (tx << 2)];
            float av[4] = {a.x, a.y, a.z, a.w};
            float bv[4] = {b.x, b.y, b.z, b.w};
#pragma unroll
            for (int i = 0; i < 4; i++)
#pragma unroll
                for (int j2 = 0; j2 < 4; j2++) s[i][j2] += av[i] * bv[j2];
        }
        __syncthreads();   // done reading KP-as-K
        // write scaled/masked scores into KP as P[k][q]
#pragma unroll
        for (int i = 0; i < 4; i++) {
#pragma unroll
            for (int j2 = 0; j2 < 4; j2++) {
                int q = ty * 4 + i;
                int kcol = tx * 4 + j2;
                float val = s[i][j2] * 0.125f;
                if (j == qi && kcol > q) val = -INFINITY;
                KP[kcol * LD + q] = val;
            }
        }
        __syncthreads();
        // per-row block max, exp, den accumulation (matches reference per-block shift)
        if (tid < 64) {
            float m = -INFINITY;
            for (int k2 = 0; k2 < 64; k2++) m = fmaxf(m, KP[k2 * LD + tid]);
            float ds = 0.0f;
            for (int k2 = 0; k2 < 64; k2++) {
                float pexp = expf(KP[k2 * LD + tid] - m);
                KP[k2 * LD + tid] = pexp;
                ds += pexp;
            }
            den[tid] += ds;
        }
        __syncthreads();
        // o[q][d] += sum_k P[k][q]*V[k][d]
#pragma unroll 8
        for (int k2 = 0; k2 < 64; k2++) {
            float4 a = *(const float4*)&KP[k2 * LD + (ty << 2)];
            float4 b = *(const float4*)&Vs[k2 * LD + (tx << 2)];
            float av[4] = {a.x, a.y, a.z, a.w};
            float bv[4] = {b.x, b.y, b.z, b.w};
#pragma unroll
            for (int i = 0; i < 4; i++)
#pragma unroll
                for (int j2 = 0; j2 < 4; j2++) o[i][j2] += av[i] * bv[j2];
        }
    }
    __syncthreads();
#pragma unroll
    for (int i = 0; i < 4; i++) {
        int q = ty * 4 + i;
        float dn = den[q] + 1e-6f;
#pragma unroll
        for (int j2 = 0; j2 < 4; j2++) {
            int d = tx * 4 + j2;
            O[(size_t)(qi * 64 + q) * kD + h * kHD + d] = o[i][j2] / dn;
        }
    }
}

// ---------------- elementwise ----------------
__global__ void add_kernel(const float* __restrict__ A, const float* __restrict__ B,
                           float* __restrict__ Y, int n) {
    int i = blockIdx.x * blockDim.x + threadIdx.x;
    if (i < n) Y[i] = A[i] + B[i];
}

__global__ void silu_mul_kernel(float* __restrict__ H1, const float* __restrict__ H3, int n) {
    int i = blockIdx.x * blockDim.x + threadIdx.x;
    if (i < n) {
        float x = H1[i];
        H1[i] = (x / (1.0f + expf(-x))) * H3[i];
    }
}

// ---------------- layernorm (row = block) ----------------
__global__ void ln_kernel(const float* __restrict__ X, const float* __restrict__ g,
                          const float* __restrict__ b, float* __restrict__ Y) {
    int row = blockIdx.x;
    int tid = threadIdx.x;  // 256
    __shared__ float red[256];
    __shared__ float s_mu, s_inv;
    const float* x = X + (size_t)row * kD;
    float s = 0.0f;
    for (int i = tid; i < kD; i += 256) s += x[i];
    red[tid] = s; __syncthreads();
    for (int st = 128; st > 0; st >>= 1) { if (tid < st) red[tid] += red[tid + st]; __syncthreads(); }
    if (tid == 0) s_mu = red[0] / (float)kD;
    __syncthreads();
    float mu = s_mu;
    float v = 0.0f;
    for (int i = tid; i < kD; i += 256) { float d = x[i] - mu; v += d * d; }
    red[tid] = v; __syncthreads();
    for (int st = 128; st > 0; st >>= 1) { if (tid < st) red[tid] += red[tid + st]; __syncthreads(); }
    if (tid == 0) s_inv = 1.0f / sqrtf(red[0] / (float)kD + 1e-5f);
    __syncthreads();
    float inv = s_inv;
    for (int i = tid; i < kD; i += 256)
        Y[(size_t)row * kD + i] = (x[i] - mu) * inv * g[i] + b[i];
}

// ---------------- gate: logits, softmax, top-2 weights, per-token variance ----------------
__global__ void gate_kernel(const float* __restrict__ X, const float* __restrict__ GW,
                            float* __restrict__ wdense, float* __restrict__ varbuf) {
    int t = blockIdx.x;
    int tid = threadIdx.x;  // 128
    __shared__ float red[128];
    __shared__ float logits[4];
    const float* x = X + (size_t)t * kD;
    float acc[4] = {0.f, 0.f, 0.f, 0.f};
    for (int d = tid; d < kD; d += 128) {
        float xv = x[d];
        acc[0] += xv * GW[0 * kD + d];
        acc[1] += xv * GW[1 * kD + d];
        acc[2] += xv * GW[2 * kD + d];
        acc[3] += xv * GW[3 * kD + d];
    }
    for (int e = 0; e < 4; e++) {
        red[tid] = acc[e]; __syncthreads();
        for (int st = 64; st > 0; st >>= 1) { if (tid < st) red[tid] += red[tid + st]; __syncthreads(); }
        if (tid == 0) logits[e] = red[0];
        __syncthreads();
    }
    if (tid == 0) {
        float l[4] = {logits[0], logits[1], logits[2], logits[3]};
        float mx = fmaxf(fmaxf(l[0], l[1]), fmaxf(l[2], l[3]));
        float pe[4], ps = 0.f;
        for (int e = 0; e < 4; e++) { pe[e] = expf(l[e] - mx); ps += pe[e]; }
        float pr[4];
        for (int e = 0; e < 4; e++) pr[e] = pe[e] / ps;
        int a = 0;
        for (int e = 1; e < 4; e++) if (pr[e] > pr[a]) a = e;
        int b2 = -1;
        for (int e = 0; e < 4; e++) { if (e == a) continue; if (b2 < 0 || pr[e] > pr[b2]) b2 = e; }
        float wsum = pr[a] + pr[b2];
        float w[4] = {0.f, 0.f, 0.f, 0.f};
        w[a] = pr[a] / wsum; w[b2] = pr[b2] / wsum;
        for (int e = 0; e < 4; e++) wdense[t * 4 + e] = w[e];
        float mu = 0.25f * (l[0] + l[1] + l[2] + l[3]);
        float vv = 0.f;
        for (int e = 0; e < 4; e++) { float d = l[e] - mu; vv += d * d; }
        varbuf[t] = vv / 3.0f;   // ddof=1
    }
}

__global__ void aux_kernel(const float* __restrict__ varbuf, float* __restrict__ out) {
    __shared__ float red[256];
    int tid = threadIdx.x;
    float s = 0.f;
    for (int i = tid; i < kS; i += 256) s += varbuf[i];
    red[tid] = s; __syncthreads();
    for (int st = 128; st > 0; st >>= 1) { if (tid < st) red[tid] += red[tid + st]; __syncthreads(); }
    if (tid == 0) out[0] = red[0] / (float)kS;
}

// ---------------- launch ----------------
extern "C" void kernel_launch(void* const* d_in, const int* in_sizes, int n_in,
                              void* d_out, int out_size) {
    const int*   tokens = (const int*)d_in[0];
    const float* emb    = (const float*)d_in[1];
    const float* wq     = (const float*)d_in[2];
    const float* wk     = (const float*)d_in[3];
    const float* wv     = (const float*)d_in[4];
    const float* wo     = (const float*)d_in[5];
    const float* ln1_g  = (const float*)d_in[6];
    const float* ln1_b  = (const float*)d_in[7];
    const float* gate_w = (const float*)d_in[8];
    const float* w1     = (const float*)d_in[9];
    const float* w2     = (const float*)d_in[10];
    const float* w3     = (const float*)d_in[11];
    const float* ln2_g  = (const float*)d_in[12];
    const float* ln2_b  = (const float*)d_in[13];
    const float* fin_g  = (const float*)d_in[14];
    const float* fin_b  = (const float*)d_in[15];
    const float* head_w = (const float*)d_in[16];
    float* out = (float*)d_out;

    float *x0, *q, *k, *v, *o, *p, *x1, *xn1, *h1, *h3, *moe, *x2, *x3, *x4, *wdense, *varbuf;
    cudaGetSymbolAddress((void**)&x0,  g_x0);
    cudaGetSymbolAddress((void**)&q,   g_q);
    cudaGetSymbolAddress((void**)&k,   g_k);
    cudaGetSymbolAddress((void**)&v,   g_v);
    cudaGetSymbolAddress((void**)&o,   g_o);
    cudaGetSymbolAddress((void**)&p,   g_p);
    cudaGetSymbolAddress((void**)&x1,  g_x1);
    cudaGetSymbolAddress((void**)&xn1, g_xn1);
    cudaGetSymbolAddress((void**)&h1,  g_h1);
    cudaGetSymbolAddress((void**)&h3,  g_h3);
    cudaGetSymbolAddress((void**)&moe, g_moe);
    cudaGetSymbolAddress((void**)&x2,  g_x2);
    cudaGetSymbolAddress((void**)&x3,  g_x3);
    cudaGetSymbolAddress((void**)&x4,  g_x4);
    cudaGetSymbolAddress((void**)&wdense, g_wdense);
    cudaGetSymbolAddress((void**)&varbuf, g_var);

    const int SD = kS * kD;
    const int SF = kS * kF;

    // embed
    embed_kernel<<<SD / 256, 256>>>(tokens, emb, x0);

    // qkv projections
    dim3 gDD(kD / 64, kS / 64);
    gemm_nt<<<gDD, 256>>>(x0, wq, q, kS, kD, kD, nullptr, 0, 0);
    gemm_nt<<<gDD, 256>>>(x0, wk, k, kS, kD, kD, nullptr, 0, 0);
    gemm_nt<<<gDD, 256>>>(x0, wv, v, kS, kD, kD, nullptr, 0, 0);

    // rope
    rope_kernel<<<(kS * kH * 32) / 256, 256>>>(q);
    rope_kernel<<<(kS * kH * 32) / 256, 256>>>(k);

    // attention
    int attn_smem = (3 * 64 * 68 + 64) * (int)sizeof(float);
    cudaFuncSetAttribute(attn_kernel, cudaFuncAttributeMaxDynamicSharedMemorySize, attn_smem);
    attn_kernel<<<dim3(kS / 64, kH), 256, attn_smem>>>(q, k, v, o);

    // output projection + residual
    gemm_nt<<<gDD, 256>>>(o, wo, p, kS, kD, kD, nullptr, 0, 0);
    add_kernel<<<(SD + 255) / 256, 256>>>(p, x0, x1, SD);

    // ln1
    ln_kernel<<<kS, 256>>>(x1, ln1_g, ln1_b, xn1);

    // gate + aux
    gate_kernel<<<kS, 128>>>(xn1, gate_w, wdense, varbuf);
    aux_kernel<<<1, 256>>>(varbuf, out + (size_t)out_size - 1);

    // MoE experts (dense, weighted accumulate)
    dim3 gFD(kF / 64, kS / 64);
    dim3 gDF(kD / 64, kS / 64);
    for (int e = 0; e < kNE; e++) {
        const float* w1e = w1 + (size_t)e * kF * kD;
        const float* w3e = w3 + (size_t)e * kF * kD;
        const float* w2e = w2 + (size_t)e * kD * kF;
        gemm_nt<<<gFD, 256>>>(xn1, w1e, h1, kS, kF, kD, nullptr, 0, 0);
        gemm_nt<<<gFD, 256>>>(xn1, w3e, h3, kS, kF, kD, nullptr, 0, 0);
        silu_mul_kernel<<<(SF + 255) / 256, 256>>>(h1, h3, SF);
        gemm_nt<<<gDF, 256>>>(h1, w2e, moe, kS, kD, kF, wdense + e, 4, e ? 1 : 0);
    }

    // residual + ln2 + final ln
    add_kernel<<<(SD + 255) / 256, 256>>>(moe, xn1, x2, SD);
    ln_kernel<<<kS, 256>>>(x2, ln2_g, ln2_b, x3);
    ln_kernel<<<kS, 256>>>(x3, fin_g, fin_b, x4);

    // LM head -> logits (written directly to d_out)
    dim3 gHead((kVOC + 63) / 64, kS / 64);
    gemm_nt<<<gHead, 256>>>(x4, head_w, out, kS, kVOC, kD, nullptr, 0, 0);
}

// round 3
// speedup vs baseline: 4.0610x; 4.0610x over previous
#include <cuda_runtime.h>
#include <math.h>
#include <stdint.h>

// ---------------- constants ----------------
#define kS   1024
#define kD   2048
#define kH   32
#define kHD  64
#define kF   8192
#define kNE  4
#define kVOC 50257

// ---------------- scratch ----------------
__device__ float g_x0 [kS*kD];
__device__ float g_q  [kS*kD];
__device__ float g_k  [kS*kD];
__device__ float g_v  [kS*kD];
__device__ float g_o  [kS*kD];
__device__ float g_p  [kS*kD];
__device__ float g_x1 [kS*kD];
__device__ float g_xn1[kS*kD];
__device__ float g_h1 [kS*kF];
__device__ float g_h3 [kS*kF];
__device__ float g_moe[kS*kD];
__device__ float g_x2 [kS*kD];
__device__ float g_x3 [kS*kD];
__device__ float g_x4 [kS*kD];
__device__ float g_wdense[kS*kNE];
__device__ float g_var[kS];

// rounded-weight scratch (tf32 RNE copies)
__device__ float g_rwq[kD*kD];
__device__ float g_rwk[kD*kD];
__device__ float g_rwv[kD*kD];
__device__ float g_rwo[kD*kD];
__device__ float g_rw1[kNE*kF*kD];
__device__ float g_rw3[kNE*kF*kD];
__device__ float g_rw2[kNE*kD*kF];
__device__ float g_rhd[kVOC*kD];

// ---------------- PTX helpers (base sm_103 only: no tcgen05) ----------------
__device__ __forceinline__ uint32_t smem_u32(const void* p) {
    uint32_t a;
    asm("{ .reg .u64 t; cvta.to.shared.u64 t, %1; cvt.u32.u64 %0, t; }" : "=r"(a) : "l"(p));
    return a;
}
__device__ __forceinline__ float rna_tf32(float x) {
    uint32_t y;
    asm("cvt.rna.tf32.f32 %0, %1;" : "=r"(y) : "f"(x));
    return __uint_as_float(y);
}
__device__ __forceinline__ void cpa16(uint32_t dst, const void* src) {
    asm volatile("cp.async.cg.shared.global [%0], [%1], 16;" :: "r"(dst), "l"(src));
}
#define CPA_COMMIT() asm volatile("cp.async.commit_group;" ::: "memory")
#define CPA_WAIT2()  asm volatile("cp.async.wait_group 2;" ::: "memory")

#define LDSM_X4(r, addr) \
    asm volatile("ldmatrix.sync.aligned.m8n8.x4.shared.b16 {%0,%1,%2,%3}, [%4];" \
        : "=r"((r)[0]), "=r"((r)[1]), "=r"((r)[2]), "=r"((r)[3]) : "r"(addr))

__device__ __forceinline__ void mma_tf32(float* c, const uint32_t* a, uint32_t b0, uint32_t b1) {
    asm volatile("mma.sync.aligned.m16n8k8.row.col.f32.tf32.tf32.f32 "
        "{%0,%1,%2,%3}, {%4,%5,%6,%7}, {%8,%9}, {%0,%1,%2,%3};"
        : "+f"(c[0]), "+f"(c[1]), "+f"(c[2]), "+f"(c[3])
        : "r"(a[0]), "r"(a[1]), "r"(a[2]), "r"(a[3]), "r"(b0), "r"(b1));
}

// ---------------- tf32 mma.sync NT GEMM ----------------
// C[M,N] = (beta?C:0) + rowScale[m]*sum_k A[m,k]*B[n,k]
// M%128==0, K%32==0, N arbitrary.
#define BM 128
#define BN 128
#define BK 32
#define NST 4
#define ASTG 16384
#define STG  32768
#define GEMM_SMEM (NST*STG)

__device__ __forceinline__ void gemm_load_stage(
    uint32_t sb, int s, int kt,
    const float* __restrict__ A, const float* __restrict__ B,
    int bm, int bn, int K, int N, int tid)
{
#pragma unroll
    for (int j = 0; j < 4; j++) {
        int idx = tid + j * 256;
        int row = idx >> 3, c4 = idx & 7;
        uint32_t sw = ((uint32_t)(c4 ^ (row & 7))) << 4;
        uint32_t base = sb + (uint32_t)s * STG + (uint32_t)(row << 7) + sw;
        cpa16(base, A + (size_t)(bm + row) * K + kt * BK + c4 * 4);
        if (bn + row < N)
            cpa16(base + ASTG, B + (size_t)(bn + row) * K + kt * BK + c4 * 4);
    }
}

__global__ void __launch_bounds__(256, 1) gemm_mma(
    const float* __restrict__ A, const float* __restrict__ B, float* __restrict__ C,
    int M, int N, int K, const float* __restrict__ rowScale, int rsStride, int beta)
{
    extern __shared__ char smraw[];
    uint32_t sb = smem_u32(smraw);
    int tid = threadIdx.x, lane = tid & 31, wid = tid >> 5;
    int wm = wid >> 2, wn = wid & 3;         // warp grid 2 (m) x 4 (n)
    int bm = blockIdx.x * BM, bn = blockIdx.y * BN;
    int KT = K / BK;

    float acc[4][4][4];
#pragma unroll
    for (int i = 0; i < 4; i++)
#pragma unroll
        for (int j = 0; j < 4; j++)
#pragma unroll
            for (int r = 0; r < 4; r++) acc[i][j][r] = 0.0f;

    // ldmatrix per-lane geometry
    int arow = lane & 15;            // A: sub row
    int ahalf = lane >> 4;           // A: k half (0/1)
    int ars = arow & 7;
    int brow = lane & 7;             // B: n row within 8
    int bq = lane >> 3;              // B: quarter 0..3
    uint32_t aBase = sb + (uint32_t)((wm * 64 + arow) << 7);
    uint32_t bBase = sb + ASTG + (uint32_t)((wn * 32 + brow) << 7);

    // prologue
#pragma unroll
    for (int s = 0; s < NST - 1; s++) {
        gemm_load_stage(sb, s, s, A, B, bm, bn, K, N, tid);
        CPA_COMMIT();
    }

    for (int kt = 0; kt < KT; kt++) {
        CPA_WAIT2();
        __syncthreads();
        int s = kt & (NST - 1);
        int ktn = kt + NST - 1;
        if (ktn < KT) gemm_load_stage(sb, ktn & (NST - 1), ktn, A, B, bm, bn, K, N, tid);
        CPA_COMMIT();

        uint32_t aS = aBase + (uint32_t)s * STG;
        uint32_t bS = bBase + (uint32_t)s * STG;
#pragma unroll
        for (int kp = 0; kp < 2; kp++) {
            uint32_t bf[4][4];
#pragma unroll
            for (int nt = 0; nt < 4; nt++)
                LDSM_X4(bf[nt], bS + (uint32_t)(nt * 8 * 128) +
                                 ((uint32_t)((kp * 4 + bq) ^ brow) << 4));
#pragma unroll
            for (int ks = 0; ks < 2; ks++) {
                int kstep = kp * 2 + ks;
                uint32_t af[4][4];
#pragma unroll
                for (int mt = 0; mt < 4; mt++)
                    LDSM_X4(af[mt], aS + (uint32_t)(mt * 16 * 128) +
                                     ((uint32_t)((kstep * 2 + ahalf) ^ ars) << 4));
#pragma unroll
                for (int mt = 0; mt < 4; mt++)
#pragma unroll
                    for (int nt = 0; nt < 4; nt++)
                        mma_tf32(acc[mt][nt], af[mt], bf[nt][ks * 2], bf[nt][ks * 2 + 1]);
            }
        }
    }

    // epilogue
    int evenN = ((N & 1) == 0);
#pragma unroll
    for (int mt = 0; mt < 4; mt++) {
        int r0 = bm + wm * 64 + mt * 16 + (lane >> 2);
        int r1 = r0 + 8;
        float s0 = rowScale ? rowScale[(size_t)r0 * rsStride] : 1.0f;
        float s1 = rowScale ? rowScale[(size_t)r1 * rsStride] : 1.0f;
#pragma unroll
        for (int nt = 0; nt < 4; nt++) {
            int n0 = bn + wn * 32 + nt * 8 + 2 * (lane & 3);
            const float* a = acc[mt][nt];
            if (evenN && n0 + 1 < N) {
                float2 v0 = make_float2(a[0] * s0, a[1] * s0);
                float2 v1 = make_float2(a[2] * s1, a[3] * s1);
                float* p0 = C + (size_t)r0 * N + n0;
                float* p1 = C + (size_t)r1 * N + n0;
                if (beta) {
                    float2 o0 = *(const float2*)p0, o1 = *(const float2*)p1;
                    v0.x += o0.x; v0.y += o0.y; v1.x += o1.x; v1.y += o1.y;
                }
                *(float2*)p0 = v0;
                *(float2*)p1 = v1;
            } else {
#pragma unroll
                for (int e = 0; e < 2; e++) {
                    int nn = n0 + e;
                    if (nn < N) {
                        float v0 = a[e] * s0, v1 = a[2 + e] * s1;
                        size_t i0 = (size_t)r0 * N + nn, i1 = (size_t)r1 * N + nn;
                        if (beta) { v0 += C[i0]; v1 += C[i1]; }
                        C[i0] = v0; C[i1] = v1;
                    }
                }
            }
        }
    }
}

// ---------------- weight rounding (fp32 -> tf32 RNE, stored as fp32) ----------------
__global__ void round_tf32_kernel(const float* __restrict__ in, float* __restrict__ out, int n4) {
    int i = blockIdx.x * blockDim.x + threadIdx.x;
    if (i < n4) {
        float4 v = ((const float4*)in)[i];
        v.x = rna_tf32(v.x); v.y = rna_tf32(v.y);
        v.z = rna_tf32(v.z); v.w = rna_tf32(v.w);
        ((float4*)out)[i] = v;
    }
}

// ---------------- embed ----------------
__global__ void embed_kernel(const int* __restrict__ tok, const float* __restrict__ emb,
                             float* __restrict__ X) {
    int i = blockIdx.x * blockDim.x + threadIdx.x;
    int t = i >> 11;
    int d = i & 2047;
    X[i] = rna_tf32(emb[(size_t)tok[t] * kD + d]);
}

// ---------------- RoPE (in-place) ----------------
__global__ void rope_kernel(float* __restrict__ X) {
    int i = blockIdx.x * blockDim.x + threadIdx.x;
    int p = i & 31;
    int h = (i >> 5) & 31;
    int t = i >> 10;
    float inv = 1.0f / powf(10000.0f, (float)(2 * p) / 64.0f);
    float ang = (float)t * inv;
    float c = cosf(ang), s = sinf(ang);
    size_t base = (size_t)t * kD + h * kHD + 2 * p;
    float x0 = X[base], x1 = X[base + 1];
    X[base]     = x0 * c - x1 * s;
    X[base + 1] = x0 * s + x1 * c;
}

// ---------------- attention (fp32, per-j-block-max exp, matches reference) ----------------
__global__ void attn_kernel(const float* __restrict__ Q, const float* __restrict__ K,
                            const float* __restrict__ V, float* __restrict__ O) {
    extern __shared__ float sm[];
    const int LD = 68;
    float* Qt  = sm;
    float* KP  = Qt + 64 * LD;
    float* Vs  = KP + 64 * LD;
    float* den = Vs + 64 * LD;
    int qi = blockIdx.x;
    int h  = blockIdx.y;
    int tid = threadIdx.x;
    int tx = tid & 15, ty = tid >> 4;

    for (int it = tid; it < 1024; it += 256) {
        int q = it >> 4;
        int d4 = (it & 15) << 2;
        float4 vq = *(const float4*)(Q + (size_t)(qi * 64 + q) * kD + h * kHD + d4);
        Qt[(d4 + 0) * LD + q] = vq.x;
        Qt[(d4 + 1) * LD + q] = vq.y;
        Qt[(d4 + 2) * LD + q] = vq.z;
        Qt[(d4 + 3) * LD + q] = vq.w;
    }
    if (tid < 64) den[tid] = 0.0f;

    float o[4][4] = {};
    for (int j = 0; j <= qi; j++) {
        __syncthreads();
        for (int it = tid; it < 1024; it += 256) {
            int r = it >> 4;
            int d4 = (it & 15) << 2;
            float4 kv = *(const float4*)(K + (size_t)(j * 64 + r) * kD + h * kHD + d4);
            KP[(d4 + 0) * LD + r] = kv.x;
            KP[(d4 + 1) * LD + r] = kv.y;
            KP[(d4 + 2) * LD + r] = kv.z;
            KP[(d4 + 3) * LD + r] = kv.w;
            float4 vv = *(const float4*)(V + (size_t)(j * 64 + r) * kD + h * kHD + d4);
            *(float4*)&Vs[r * LD + d4] = vv;
        }
        __syncthreads();
        float s[4][4] = {};
#pragma unroll 8
        for (int d = 0; d < 64; d++) {
            float4 a = *(const float4*)&Qt[d * LD + (ty << 2)];
            float4 b = *(const float4*)&KP[d * LD + (tx << 2)];
            float av[4] = {a.x, a.y, a.z, a.w};
            float bv[4] = {b.x, b.y, b.z, b.w};
#pragma unroll
            for (int i = 0; i < 4; i++)
#pragma unroll
                for (int j2 = 0; j2 < 4; j2++) s[i][j2] += av[i] * bv[j2];
        }
        __syncthreads();
#pragma unroll
        for (int i = 0; i < 4; i++) {
#pragma unroll
            for (int j2 = 0; j2 < 4; j2++) {
                int q = ty * 4 + i;
                int kcol = tx * 4 + j2;
                float val = s[i][j2] * 0.125f;
                if (j == qi && kcol > q) val = -INFINITY;
                KP[kcol * LD + q] = val;
            }
        }
        __syncthreads();
        if (tid < 64) {
            float m = -INFINITY;
            for (int k2 = 0; k2 < 64; k2++) m = fmaxf(m, KP[k2 * LD + tid]);
            float ds = 0.0f;
            for (int k2 = 0; k2 < 64; k2++) {
                float pexp = expf(KP[k2 * LD + tid] - m);
                KP[k2 * LD + tid] = pexp;
                ds += pexp;
            }
            den[tid] += ds;
        }
        __syncthreads();
#pragma unroll 8
        for (int k2 = 0; k2 < 64; k2++) {
            float4 a = *(const float4*)&KP[k2 * LD + (ty << 2)];
            float4 b = *(const float4*)&Vs[k2 * LD + (tx << 2)];
            float av[4] = {a.x, a.y, a.z, a.w};
            float bv[4] = {b.x, b.y, b.z, b.w};
#pragma unroll
            for (int i = 0; i < 4; i++)
#pragma unroll
                for (int j2 = 0; j2 < 4; j2++) o[i][j2] += av[i] * bv[j2];
        }
    }
    __syncthreads();
#pragma unroll
    for (int i = 0; i < 4; i++) {
        int q = ty * 4 + i;
        float dn = den[q] + 1e-6f;
#pragma unroll
        for (int j2 = 0; j2 < 4; j2++) {
            int d = tx * 4 + j2;
            O[(size_t)(qi * 64 + q) * kD + h * kHD + d] = rna_tf32(o[i][j2] / dn);
        }
    }
}

// ---------------- elementwise ----------------
__global__ void add_kernel(const float* __restrict__ A, const float* __restrict__ B,
                           float* __restrict__ Y, int n) {
    int i = blockIdx.x * blockDim.x + threadIdx.x;
    if (i < n) Y[i] = A[i] + B[i];
}

__global__ void silu_mul_kernel(float* __restrict__ H1, const float* __restrict__ H3, int n) {
    int i = blockIdx.x * blockDim.x + threadIdx.x;
    if (i < n) {
        float x = H1[i];
        H1[i] = rna_tf32((x / (1.0f + expf(-x))) * H3[i]);
    }
}

// ---------------- layernorm ----------------
__global__ void ln_kernel(const float* __restrict__ X, const float* __restrict__ g,
                          const float* __restrict__ b, float* __restrict__ Y, int doRound) {
    int row = blockIdx.x;
    int tid = threadIdx.x;
    __shared__ float red[256];
    __shared__ float s_mu, s_inv;
    const float* x = X + (size_t)row * kD;
    float s = 0.0f;
    for (int i = tid; i < kD; i += 256) s += x[i];
    red[tid] = s; __syncthreads();
    for (int st = 128; st > 0; st >>= 1) { if (tid < st) red[tid] += red[tid + st]; __syncthreads(); }
    if (tid == 0) s_mu = red[0] / (float)kD;
    __syncthreads();
    float mu = s_mu;
    float v = 0.0f;
    for (int i = tid; i < kD; i += 256) { float d = x[i] - mu; v += d * d; }
    red[tid] = v; __syncthreads();
    for (int st = 128; st > 0; st >>= 1) { if (tid < st) red[tid] += red[tid + st]; __syncthreads(); }
    if (tid == 0) s_inv = 1.0f / sqrtf(red[0] / (float)kD + 1e-5f);
    __syncthreads();
    float inv = s_inv;
    for (int i = tid; i < kD; i += 256) {
        float y = (x[i] - mu) * inv * g[i] + b[i];
        Y[(size_t)row * kD + i] = doRound ? rna_tf32(y) : y;
    }
}

// ---------------- gate ----------------
__global__ void gate_kernel(const float* __restrict__ X, const float* __restrict__ GW,
                            float* __restrict__ wdense, float* __restrict__ varbuf) {
    int t = blockIdx.x;
    int tid = threadIdx.x;
    __shared__ float red[128];
    __shared__ float logits[4];
    const float* x = X + (size_t)t * kD;
    float acc[4] = {0.f, 0.f, 0.f, 0.f};
    for (int d = tid; d < kD; d += 128) {
        float xv = x[d];
        acc[0] += xv * GW[0 * kD + d];
        acc[1] += xv * GW[1 * kD + d];
        acc[2] += xv * GW[2 * kD + d];
        acc[3] += xv * GW[3 * kD + d];
    }
    for (int e = 0; e < 4; e++) {
        red[tid] = acc[e]; __syncthreads();
        for (int st = 64; st > 0; st >>= 1) { if (tid < st) red[tid] += red[tid + st]; __syncthreads(); }
        if (tid == 0) logits[e] = red[0];
        __syncthreads();
    }
    if (tid == 0) {
        float l[4] = {logits[0], logits[1], logits[2], logits[3]};
        float mx = fmaxf(fmaxf(l[0], l[1]), fmaxf(l[2], l[3]));
        float pe[4], ps = 0.f;
        for (int e = 0; e < 4; e++) { pe[e] = expf(l[e] - mx); ps += pe[e]; }
        float pr[4];
        for (int e = 0; e < 4; e++) pr[e] = pe[e] / ps;
        int a = 0;
        for (int e = 1; e < 4; e++) if (pr[e] > pr[a]) a = e;
        int b2 = -1;
        for (int e = 0; e < 4; e++) { if (e == a) continue; if (b2 < 0 || pr[e] > pr[b2]) b2 = e; }
        float wsum = pr[a] + pr[b2];
        float w[4] = {0.f, 0.f, 0.f, 0.f};
        w[a] = pr[a] / wsum; w[b2] = pr[b2] / wsum;
        for (int e = 0; e < 4; e++) wdense[t * 4 + e] = w[e];
        float mu = 0.25f * (l[0] + l[1] + l[2] + l[3]);
        float vv = 0.f;
        for (int e = 0; e < 4; e++) { float d = l[e] - mu; vv += d * d; }
        varbuf[t] = vv / 3.0f;
    }
}

__global__ void aux_kernel(const float* __restrict__ varbuf, float* __restrict__ out) {
    __shared__ float red[256];
    int tid = threadIdx.x;
    float s = 0.f;
    for (int i = tid; i < kS; i += 256) s += varbuf[i];
    red[tid] = s; __syncthreads();
    for (int st = 128; st > 0; st >>= 1) { if (tid < st) red[tid] += red[tid + st]; __syncthreads(); }
    if (tid == 0) out[0] = red[0] / (float)kS;
}

// ---------------- launch ----------------
extern "C" void kernel_launch(void* const* d_in, const int* in_sizes, int n_in,
                              void* d_out, int out_size) {
    const int*   tokens = (const int*)d_in[0];
    const float* emb    = (const float*)d_in[1];
    const float* wq     = (const float*)d_in[2];
    const float* wk     = (const float*)d_in[3];
    const float* wv     = (const float*)d_in[4];
    const float* wo     = (const float*)d_in[5];
    const float* ln1_g  = (const float*)d_in[6];
    const float* ln1_b  = (const float*)d_in[7];
    const float* gate_w = (const float*)d_in[8];
    const float* w1     = (const float*)d_in[9];
    const float* w2     = (const float*)d_in[10];
    const float* w3     = (const float*)d_in[11];
    const float* ln2_g  = (const float*)d_in[12];
    const float* ln2_b  = (const float*)d_in[13];
    const float* fin_g  = (const float*)d_in[14];
    const float* fin_b  = (const float*)d_in[15];
    const float* head_w = (const float*)d_in[16];
    float* out = (float*)d_out;

    float *x0, *q, *k, *v, *o, *p, *x1, *xn1, *h1, *h3, *moe, *x2, *x3, *x4, *wdense, *varbuf;
    float *rwq, *rwk, *rwv, *rwo, *rw1, *rw3, *rw2, *rhd;
    cudaGetSymbolAddress((void**)&x0,  g_x0);
    cudaGetSymbolAddress((void**)&q,   g_q);
    cudaGetSymbolAddress((void**)&k,   g_k);
    cudaGetSymbolAddress((void**)&v,   g_v);
    cudaGetSymbolAddress((void**)&o,   g_o);
    cudaGetSymbolAddress((void**)&p,   g_p);
    cudaGetSymbolAddress((void**)&x1,  g_x1);
    cudaGetSymbolAddress((void**)&xn1, g_xn1);
    cudaGetSymbolAddress((void**)&h1,  g_h1);
    cudaGetSymbolAddress((void**)&h3,  g_h3);
    cudaGetSymbolAddress((void**)&moe, g_moe);
    cudaGetSymbolAddress((void**)&x2,  g_x2);
    cudaGetSymbolAddress((void**)&x3,  g_x3);
    cudaGetSymbolAddress((void**)&x4,  g_x4);
    cudaGetSymbolAddress((void**)&wdense, g_wdense);
    cudaGetSymbolAddress((void**)&varbuf, g_var);
    cudaGetSymbolAddress((void**)&rwq, g_rwq);
    cudaGetSymbolAddress((void**)&rwk, g_rwk);
    cudaGetSymbolAddress((void**)&rwv, g_rwv);
    cudaGetSymbolAddress((void**)&rwo, g_rwo);
    cudaGetSymbolAddress((void**)&rw1, g_rw1);
    cudaGetSymbolAddress((void**)&rw3, g_rw3);
    cudaGetSymbolAddress((void**)&rw2, g_rw2);
    cudaGetSymbolAddress((void**)&rhd, g_rhd);

    const int SD = kS * kD;
    const int SF = kS * kF;

    cudaFuncSetAttribute(gemm_mma, cudaFuncAttributeMaxDynamicSharedMemorySize, GEMM_SMEM);

    // ---- round weights to tf32 (RNE) ----
    {
        int nDD = kD * kD / 4;
        round_tf32_kernel<<<(nDD + 255) / 256, 256>>>(wq, rwq, nDD);
        round_tf32_kernel<<<(nDD + 255) / 256, 256>>>(wk, rwk, nDD);
        round_tf32_kernel<<<(nDD + 255) / 256, 256>>>(wv, rwv, nDD);
        round_tf32_kernel<<<(nDD + 255) / 256, 256>>>(wo, rwo, nDD);
        int nFD = kNE * kF * kD / 4;
        round_tf32_kernel<<<(nFD + 255) / 256, 256>>>(w1, rw1, nFD);
        round_tf32_kernel<<<(nFD + 255) / 256, 256>>>(w3, rw3, nFD);
        round_tf32_kernel<<<(nFD + 255) / 256, 256>>>(w2, rw2, nFD);
        int nHD = kVOC * kD / 4;
        round_tf32_kernel<<<(nHD + 255) / 256, 256>>>(head_w, rhd, nHD);
    }

    // embed (tf32-rounded)
    embed_kernel<<<SD / 256, 256>>>(tokens, emb, x0);

    // qkv projections
    dim3 gDD(kS / 128, kD / 128);   // M tiles fastest -> B panels shared in L2
    gemm_mma<<<gDD, 256, GEMM_SMEM>>>(x0, rwq, q, kS, kD, kD, nullptr, 0, 0);
    gemm_mma<<<gDD, 256, GEMM_SMEM>>>(x0, rwk, k, kS, kD, kD, nullptr, 0, 0);
    gemm_mma<<<gDD, 256, GEMM_SMEM>>>(x0, rwv, v, kS, kD, kD, nullptr, 0, 0);

    // rope
    rope_kernel<<<(kS * kH * 32) / 256, 256>>>(q);
    rope_kernel<<<(kS * kH * 32) / 256, 256>>>(k);

    // attention
    int attn_smem = (3 * 64 * 68 + 64) * (int)sizeof(float);
    cudaFuncSetAttribute(attn_kernel, cudaFuncAttributeMaxDynamicSharedMemorySize, attn_smem);
    attn_kernel<<<dim3(kS / 64, kH), 256, attn_smem>>>(q, k, v, o);

    // output projection + residual
    gemm_mma<<<gDD, 256, GEMM_SMEM>>>(o, rwo, p, kS, kD, kD, nullptr, 0, 0);
    add_kernel<<<(SD + 255) / 256, 256>>>(p, x0, x1, SD);

    // ln1 (rounded: feeds MoE GEMMs)
    ln_kernel<<<kS, 256>>>(x1, ln1_g, ln1_b, xn1, 1);

    // gate + aux
    gate_kernel<<<kS, 128>>>(xn1, gate_w, wdense, varbuf);
    aux_kernel<<<1, 256>>>(varbuf, out + (size_t)out_size - 1);

    // MoE experts
    dim3 gFD(kS / 128, kF / 128);
    dim3 gDF(kS / 128, kD / 128);
    for (int e = 0; e < kNE; e++) {
        const float* w1e = rw1 + (size_t)e * kF * kD;
        const float* w3e = rw3 + (size_t)e * kF * kD;
        const float* w2e = rw2 + (size_t)e * kD * kF;
        gemm_mma<<<gFD, 256, GEMM_SMEM>>>(xn1, w1e, h1, kS, kF, kD, nullptr, 0, 0);
        gemm_mma<<<gFD, 256, GEMM_SMEM>>>(xn1, w3e, h3, kS, kF, kD, nullptr, 0, 0);
        silu_mul_kernel<<<(SF + 255) / 256, 256>>>(h1, h3, SF);
        gemm_mma<<<gDF, 256, GEMM_SMEM>>>(h1, w2e, moe, kS, kD, kF, wdense + e, 4, e ? 1 : 0);
    }

    // residual + ln2 + final ln (rounded: feeds head GEMM)
    add_kernel<<<(SD + 255) / 256, 256>>>(moe, xn1, x2, SD);
    ln_kernel<<<kS, 256>>>(x2, ln2_g, ln2_b, x3, 0);
    ln_kernel<<<kS, 256>>>(x3, fin_g, fin_b, x4, 1);

    // LM head
    dim3 gHead(kS / 128, (kVOC + 127) / 128);
    gemm_mma<<<gHead, 256, GEMM_SMEM>>>(x4, rhd, out, kS, kVOC, kD, nullptr, 0, 0);
}

// round 4
// speedup vs baseline: 4.5802x; 1.1279x over previous
#include <cuda_runtime.h>
#include <math.h>
#include <stdint.h>

// ---------------- constants ----------------
#define kS   1024
#define kD   2048
#define kH   32
#define kHD  64
#define kF   8192
#define kNE  4
#define kVOC 50257

// ---------------- scratch ----------------
__device__ float g_x0 [kS*kD];
__device__ float g_q  [kS*kD];
__device__ float g_k  [kS*kD];
__device__ float g_v  [kS*kD];
__device__ float g_o  [kS*kD];
__device__ float g_x1 [kS*kD];
__device__ float g_xn1[kS*kD];
__device__ float g_h1 [kS*kF];
__device__ float g_moe[kS*kD];
__device__ float g_x2 [kS*kD];
__device__ float g_x3 [kS*kD];
__device__ float g_x4 [kS*kD];
__device__ float g_wdense[kS*kNE];
__device__ float g_var[kS];

// ---------------- PTX helpers (base sm_103: no tcgen05) ----------------
__device__ __forceinline__ uint32_t smem_u32(const void* p) {
    uint32_t a;
    asm("{ .reg .u64 t; cvta.to.shared.u64 t, %1; cvt.u32.u64 %0, t; }" : "=r"(a) : "l"(p));
    return a;
}
__device__ __forceinline__ float rna_tf32(float x) {
    uint32_t y;
    asm("cvt.rna.tf32.f32 %0, %1;" : "=r"(y) : "f"(x));
    return __uint_as_float(y);
}
__device__ __forceinline__ uint32_t rna_tf32_bits(uint32_t x) {
    uint32_t y;
    asm("cvt.rna.tf32.f32 %0, %1;" : "=r"(y) : "f"(__uint_as_float(x)));
    return y;
}
__device__ __forceinline__ void cpa16(uint32_t dst, const void* src) {
    asm volatile("cp.async.cg.shared.global [%0], [%1], 16;" :: "r"(dst), "l"(src));
}
#define CPA_COMMIT() asm volatile("cp.async.commit_group;" ::: "memory")
#define CPA_WAIT1()  asm volatile("cp.async.wait_group 1;" ::: "memory")

#define LDSM_X4(r, addr) \
    asm volatile("ldmatrix.sync.aligned.m8n8.x4.shared.b16 {%0,%1,%2,%3}, [%4];" \
        : "=r"((r)[0]), "=r"((r)[1]), "=r"((r)[2]), "=r"((r)[3]) : "r"(addr))

__device__ __forceinline__ void mma_tf32(float* c, const uint32_t* a, uint32_t b0, uint32_t b1) {
    asm volatile("mma.sync.aligned.m16n8k8.row.col.f32.tf32.tf32.f32 "
        "{%0,%1,%2,%3}, {%4,%5,%6,%7}, {%8,%9}, {%0,%1,%2,%3};"
        : "+f"(c[0]), "+f"(c[1]), "+f"(c[2]), "+f"(c[3])
        : "r"(a[0]), "r"(a[1]), "r"(a[2]), "r"(a[3]), "r"(b0), "r"(b1));
}

// ---------------- tf32 mma.sync NT GEMM ----------------
// C[m,n] = rowScale[m]*( sum_k A[m,k]*B[n,k] ) (+ C if beta)
// fmode 1: += F[m,n]  (residual)
// fmode 2: C = rna_tf32( silu(F[m,n]) * acc )
// B is rounded to tf32 (RNE) in registers; A must already be tf32.
#define BM 128
#define BN 128
#define BK 32
#define NST 3
#define ASTG 16384
#define STG  32768
#define GEMM_SMEM (NST*STG)

__device__ __forceinline__ void gemm_load_stage(
    uint32_t sb, int s, int kt,
    const float* __restrict__ A, const float* __restrict__ B,
    int bm, int bn, int K, int N, int tid)
{
#pragma unroll
    for (int j = 0; j < 4; j++) {
        int idx = tid + j * 256;
        int row = idx >> 3, c4 = idx & 7;
        uint32_t sw = ((uint32_t)(c4 ^ (row & 7))) << 4;
        uint32_t base = sb + (uint32_t)s * STG + (uint32_t)(row << 7) + sw;
        cpa16(base, A + (size_t)(bm + row) * K + kt * BK + c4 * 4);
        if (bn + row < N)
            cpa16(base + ASTG, B + (size_t)(bn + row) * K + kt * BK + c4 * 4);
    }
}

__global__ void __launch_bounds__(256, 2) gemm_mma(
    const float* __restrict__ A, const float* __restrict__ B, float* __restrict__ C,
    int M, int N, int K, const float* __restrict__ rowScale, int rsStride, int beta,
    const float* __restrict__ F, int fmode)
{
    extern __shared__ char smraw[];
    uint32_t sb = smem_u32(smraw);
    int tid = threadIdx.x, lane = tid & 31, wid = tid >> 5;
    int wm = wid >> 2, wn = wid & 3;         // warp grid 2 (m) x 4 (n)
    int bm = blockIdx.x * BM, bn = blockIdx.y * BN;
    int KT = K / BK;

    float acc[4][4][4];
#pragma unroll
    for (int i = 0; i < 4; i++)
#pragma unroll
        for (int j = 0; j < 4; j++)
#pragma unroll
            for (int r = 0; r < 4; r++) acc[i][j][r] = 0.0f;

    int arow = lane & 15;
    int ahalf = lane >> 4;
    int ars = arow & 7;
    int brow = lane & 7;
    int bq = lane >> 3;
    uint32_t aBase = sb + (uint32_t)((wm * 64 + arow) << 7);
    uint32_t bBase = sb + ASTG + (uint32_t)((wn * 32 + brow) << 7);

    // prologue: stages 0..NST-2
#pragma unroll
    for (int s = 0; s < NST - 1; s++) {
        gemm_load_stage(sb, s, s, A, B, bm, bn, K, N, tid);
        CPA_COMMIT();
    }

    int scomp = 0, sload = NST - 1;
    for (int kt = 0; kt < KT; kt++) {
        CPA_WAIT1();
        __syncthreads();
        int ktn = kt + NST - 1;
        if (ktn < KT) gemm_load_stage(sb, sload, ktn, A, B, bm, bn, K, N, tid);
        CPA_COMMIT();

        uint32_t aS = aBase + (uint32_t)scomp * STG;
        uint32_t bS = bBase + (uint32_t)scomp * STG;
#pragma unroll
        for (int kp = 0; kp < 2; kp++) {
            uint32_t bf[4][4];
#pragma unroll
            for (int nt = 0; nt < 4; nt++) {
                LDSM_X4(bf[nt], bS + (uint32_t)(nt * 8 * 128) +
                                 ((uint32_t)((kp * 4 + bq) ^ brow) << 4));
#pragma unroll
                for (int r = 0; r < 4; r++) bf[nt][r] = rna_tf32_bits(bf[nt][r]);
            }
#pragma unroll
            for (int ks = 0; ks < 2; ks++) {
                int kstep = kp * 2 + ks;
                uint32_t af[4][4];
#pragma unroll
                for (int mt = 0; mt < 4; mt++)
                    LDSM_X4(af[mt], aS + (uint32_t)(mt * 16 * 128) +
                                     ((uint32_t)((kstep * 2 + ahalf) ^ ars) << 4));
#pragma unroll
                for (int mt = 0; mt < 4; mt++)
#pragma unroll
                    for (int nt = 0; nt < 4; nt++)
                        mma_tf32(acc[mt][nt], af[mt], bf[nt][ks * 2], bf[nt][ks * 2 + 1]);
            }
        }
        scomp = (scomp + 1 == NST) ? 0 : scomp + 1;
        sload = (sload + 1 == NST) ? 0 : sload + 1;
    }

    // epilogue
    int evenN = ((N & 1) == 0);
#pragma unroll
    for (int mt = 0; mt < 4; mt++) {
        int r0 = bm + wm * 64 + mt * 16 + (lane >> 2);
        int r1 = r0 + 8;
        float s0 = rowScale ? rowScale[(size_t)r0 * rsStride] : 1.0f;
        float s1 = rowScale ? rowScale[(size_t)r1 * rsStride] : 1.0f;
#pragma unroll
        for (int nt = 0; nt < 4; nt++) {
            int n0 = bn + wn * 32 + nt * 8 + 2 * (lane & 3);
            const float* a = acc[mt][nt];
            if (evenN && n0 + 1 < N) {
                size_t i0 = (size_t)r0 * N + n0, i1 = (size_t)r1 * N + n0;
                float2 v0 = make_float2(a[0] * s0, a[1] * s0);
                float2 v1 = make_float2(a[2] * s1, a[3] * s1);
                if (beta) {
                    float2 o0 = *(const float2*)(C + i0), o1 = *(const float2*)(C + i1);
                    v0.x += o0.x; v0.y += o0.y; v1.x += o1.x; v1.y += o1.y;
                }
                if (fmode == 1) {
                    float2 f0 = *(const float2*)(F + i0), f1 = *(const float2*)(F + i1);
                    v0.x += f0.x; v0.y += f0.y; v1.x += f1.x; v1.y += f1.y;
                } else if (fmode == 2) {
                    float2 f0 = *(const float2*)(F + i0), f1 = *(const float2*)(F + i1);
                    v0.x = rna_tf32(f0.x / (1.0f + expf(-f0.x)) * v0.x);
                    v0.y = rna_tf32(f0.y / (1.0f + expf(-f0.y)) * v0.y);
                    v1.x = rna_tf32(f1.x / (1.0f + expf(-f1.x)) * v1.x);
                    v1.y = rna_tf32(f1.y / (1.0f + expf(-f1.y)) * v1.y);
                }
                *(float2*)(C + i0) = v0;
                *(float2*)(C + i1) = v1;
            } else {
#pragma unroll
                for (int e = 0; e < 2; e++) {
                    int nn = n0 + e;
                    if (nn < N) {
                        size_t i0 = (size_t)r0 * N + nn, i1 = (size_t)r1 * N + nn;
                        float v0 = a[e] * s0, v1 = a[2 + e] * s1;
                        if (beta) { v0 += C[i0]; v1 += C[i1]; }
                        if (fmode == 1) { v0 += F[i0]; v1 += F[i1]; }
                        else if (fmode == 2) {
                            float f0 = F[i0], f1 = F[i1];
                            v0 = rna_tf32(f0 / (1.0f + expf(-f0)) * v0);
                            v1 = rna_tf32(f1 / (1.0f + expf(-f1)) * v1);
                        }
                        C[i0] = v0; C[i1] = v1;
                    }
                }
            }
        }
    }
}

// ---------------- embed ----------------
__global__ void embed_kernel(const int* __restrict__ tok, const float* __restrict__ emb,
                             float* __restrict__ X) {
    int i = blockIdx.x * blockDim.x + threadIdx.x;
    int t = i >> 11;
    int d = i & 2047;
    X[i] = rna_tf32(emb[(size_t)tok[t] * kD + d]);
}

// ---------------- RoPE (in-place) ----------------
__global__ void rope_kernel(float* __restrict__ X) {
    int i = blockIdx.x * blockDim.x + threadIdx.x;
    int p = i & 31;
    int h = (i >> 5) & 31;
    int t = i >> 10;
    float inv = 1.0f / powf(10000.0f, (float)(2 * p) / 64.0f);
    float ang = (float)t * inv;
    float c = cosf(ang), s = sinf(ang);
    size_t base = (size_t)t * kD + h * kHD + 2 * p;
    float x0 = X[base], x1 = X[base + 1];
    X[base]     = x0 * c - x1 * s;
    X[base + 1] = x0 * s + x1 * c;
}

// ---------------- attention (fp32, per-j-block-max exp, matches reference) ----------------
__global__ void attn_kernel(const float* __restrict__ Q, const float* __restrict__ K,
                            const float* __restrict__ V, float* __restrict__ O) {
    extern __shared__ float sm[];
    const int LD = 68;
    float* Qt  = sm;
    float* KP  = Qt + 64 * LD;
    float* Vs  = KP + 64 * LD;
    float* den = Vs + 64 * LD;
    int qi = blockIdx.x;
    int h  = blockIdx.y;
    int tid = threadIdx.x;
    int tx = tid & 15, ty = tid >> 4;

    for (int it = tid; it < 1024; it += 256) {
        int q = it >> 4;
        int d4 = (it & 15) << 2;
        float4 vq = *(const float4*)(Q + (size_t)(qi * 64 + q) * kD + h * kHD + d4);
        Qt[(d4 + 0) * LD + q] = vq.x;
        Qt[(d4 + 1) * LD + q] = vq.y;
        Qt[(d4 + 2) * LD + q] = vq.z;
        Qt[(d4 + 3) * LD + q] = vq.w;
    }
    if (tid < 64) den[tid] = 0.0f;

    float o[4][4] = {};
    for (int j = 0; j <= qi; j++) {
        __syncthreads();
        for (int it = tid; it < 1024; it += 256) {
            int r = it >> 4;
            int d4 = (it & 15) << 2;
            float4 kv = *(const float4*)(K + (size_t)(j * 64 + r) * kD + h * kHD + d4);
            KP[(d4 + 0) * LD + r] = kv.x;
            KP[(d4 + 1) * LD + r] = kv.y;
            KP[(d4 + 2) * LD + r] = kv.z;
            KP[(d4 + 3) * LD + r] = kv.w;
            float4 vv = *(const float4*)(V + (size_t)(j * 64 + r) * kD + h * kHD + d4);
            *(float4*)&Vs[r * LD + d4] = vv;
        }
        __syncthreads();
        float s[4][4] = {};
#pragma unroll 8
        for (int d = 0; d < 64; d++) {
            float4 a = *(const float4*)&Qt[d * LD + (ty << 2)];
            float4 b = *(const float4*)&KP[d * LD + (tx << 2)];
            float av[4] = {a.x, a.y, a.z, a.w};
            float bv[4] = {b.x, b.y, b.z, b.w};
#pragma unroll
            for (int i = 0; i < 4; i++)
#pragma unroll
                for (int j2 = 0; j2 < 4; j2++) s[i][j2] += av[i] * bv[j2];
        }
        __syncthreads();
#pragma unroll
        for (int i = 0; i < 4; i++) {
#pragma unroll
            for (int j2 = 0; j2 < 4; j2++) {
                int q = ty * 4 + i;
                int kcol = tx * 4 + j2;
                float val = s[i][j2] * 0.125f;
                if (j == qi && kcol > q) val = -INFINITY;
                KP[kcol * LD + q] = val;
            }
        }
        __syncthreads();
        if (tid < 64) {
            float m = -INFINITY;
            for (int k2 = 0; k2 < 64; k2++) m = fmaxf(m, KP[k2 * LD + tid]);
            float ds = 0.0f;
            for (int k2 = 0; k2 < 64; k2++) {
                float pexp = expf(KP[k2 * LD + tid] - m);
                KP[k2 * LD + tid] = pexp;
                ds += pexp;
            }
            den[tid] += ds;
        }
        __syncthreads();
#pragma unroll 8
        for (int k2 = 0; k2 < 64; k2++) {
            float4 a = *(const float4*)&KP[k2 * LD + (ty << 2)];
            float4 b = *(const float4*)&Vs[k2 * LD + (tx << 2)];
            float av[4] = {a.x, a.y, a.z, a.w};
            float bv[4] = {b.x, b.y, b.z, b.w};
#pragma unroll
            for (int i = 0; i < 4; i++)
#pragma unroll
                for (int j2 = 0; j2 < 4; j2++) o[i][j2] += av[i] * bv[j2];
        }
    }
    __syncthreads();
#pragma unroll
    for (int i = 0; i < 4; i++) {
        int q = ty * 4 + i;
        float dn = den[q] + 1e-6f;
#pragma unroll
        for (int j2 = 0; j2 < 4; j2++) {
            int d = tx * 4 + j2;
            O[(size_t)(qi * 64 + q) * kD + h * kHD + d] = rna_tf32(o[i][j2] / dn);
        }
    }
}

// ---------------- elementwise ----------------
__global__ void add_kernel(const float* __restrict__ A, const float* __restrict__ B,
                           float* __restrict__ Y, int n) {
    int i = blockIdx.x * blockDim.x + threadIdx.x;
    if (i < n) Y[i] = A[i] + B[i];
}

// ---------------- layernorm ----------------
__global__ void ln_kernel(const float* __restrict__ X, const float* __restrict__ g,
                          const float* __restrict__ b, float* __restrict__ Y, int doRound) {
    int row = blockIdx.x;
    int tid = threadIdx.x;
    __shared__ float red[256];
    __shared__ float s_mu, s_inv;
    const float* x = X + (size_t)row * kD;
    float s = 0.0f;
    for (int i = tid; i < kD; i += 256) s += x[i];
    red[tid] = s; __syncthreads();
    for (int st = 128; st > 0; st >>= 1) { if (tid < st) red[tid] += red[tid + st]; __syncthreads(); }
    if (tid == 0) s_mu = red[0] / (float)kD;
    __syncthreads();
    float mu = s_mu;
    float v = 0.0f;
    for (int i = tid; i < kD; i += 256) { float d = x[i] - mu; v += d * d; }
    red[tid] = v; __syncthreads();
    for (int st = 128; st > 0; st >>= 1) { if (tid < st) red[tid] += red[tid + st]; __syncthreads(); }
    if (tid == 0) s_inv = 1.0f / sqrtf(red[0] / (float)kD + 1e-5f);
    __syncthreads();
    float inv = s_inv;
    for (int i = tid; i < kD; i += 256) {
        float y = (x[i] - mu) * inv * g[i] + b[i];
        Y[(size_t)row * kD + i] = doRound ? rna_tf32(y) : y;
    }
}

// ---------------- gate ----------------
__global__ void gate_kernel(const float* __restrict__ X, const float* __restrict__ GW,
                            float* __restrict__ wdense, float* __restrict__ varbuf) {
    int t = blockIdx.x;
    int tid = threadIdx.x;
    __shared__ float red[128];
    __shared__ float logits[4];
    const float* x = X + (size_t)t * kD;
    float acc[4] = {0.f, 0.f, 0.f, 0.f};
    for (int d = tid; d < kD; d += 128) {
        float xv = x[d];
        acc[0] += xv * GW[0 * kD + d];
        acc[1] += xv * GW[1 * kD + d];
        acc[2] += xv * GW[2 * kD + d];
        acc[3] += xv * GW[3 * kD + d];
    }
    for (int e = 0; e < 4; e++) {
        red[tid] = acc[e]; __syncthreads();
        for (int st = 64; st > 0; st >>= 1) { if (tid < st) red[tid] += red[tid + st]; __syncthreads(); }
        if (tid == 0) logits[e] = red[0];
        __syncthreads();
    }
    if (tid == 0) {
        float l[4] = {logits[0], logits[1], logits[2], logits[3]};
        float mx = fmaxf(fmaxf(l[0], l[1]), fmaxf(l[2], l[3]));
        float pe[4], ps = 0.f;
        for (int e = 0; e < 4; e++) { pe[e] = expf(l[e] - mx); ps += pe[e]; }
        float pr[4];
        for (int e = 0; e < 4; e++) pr[e] = pe[e] / ps;
        int a = 0;
        for (int e = 1; e < 4; e++) if (pr[e] > pr[a]) a = e;
        int b2 = -1;
        for (int e = 0; e < 4; e++) { if (e == a) continue; if (b2 < 0 || pr[e] > pr[b2]) b2 = e; }
        float wsum = pr[a] + pr[b2];
        float w[4] = {0.f, 0.f, 0.f, 0.f};
        w[a] = pr[a] / wsum; w[b2] = pr[b2] / wsum;
        for (int e = 0; e < 4; e++) wdense[t * 4 + e] = w[e];
        float mu = 0.25f * (l[0] + l[1] + l[2] + l[3]);
        float vv = 0.f;
        for (int e = 0; e < 4; e++) { float d = l[e] - mu; vv += d * d; }
        varbuf[t] = vv / 3.0f;
    }
}

__global__ void aux_kernel(const float* __restrict__ varbuf, float* __restrict__ out) {
    __shared__ float red[256];
    int tid = threadIdx.x;
    float s = 0.f;
    for (int i = tid; i < kS; i += 256) s += varbuf[i];
    red[tid] = s; __syncthreads();
    for (int st = 128; st > 0; st >>= 1) { if (tid < st) red[tid] += red[tid + st]; __syncthreads(); }
    if (tid == 0) out[0] = red[0] / (float)kS;
}

// ---------------- launch ----------------
extern "C" void kernel_launch(void* const* d_in, const int* in_sizes, int n_in,
                              void* d_out, int out_size) {
    const int*   tokens = (const int*)d_in[0];
    const float* emb    = (const float*)d_in[1];
    const float* wq     = (const float*)d_in[2];
    const float* wk     = (const float*)d_in[3];
    const float* wv     = (const float*)d_in[4];
    const float* wo     = (const float*)d_in[5];
    const float* ln1_g  = (const float*)d_in[6];
    const float* ln1_b  = (const float*)d_in[7];
    const float* gate_w = (const float*)d_in[8];
    const float* w1     = (const float*)d_in[9];
    const float* w2     = (const float*)d_in[10];
    const float* w3     = (const float*)d_in[11];
    const float* ln2_g  = (const float*)d_in[12];
    const float* ln2_b  = (const float*)d_in[13];
    const float* fin_g  = (const float*)d_in[14];
    const float* fin_b  = (const float*)d_in[15];
    const float* head_w = (const float*)d_in[16];
    float* out = (float*)d_out;

    float *x0, *q, *k, *v, *o, *x1, *xn1, *h1, *moe, *x2, *x3, *x4, *wdense, *varbuf;
    cudaGetSymbolAddress((void**)&x0,  g_x0);
    cudaGetSymbolAddress((void**)&q,   g_q);
    cudaGetSymbolAddress((void**)&k,   g_k);
    cudaGetSymbolAddress((void**)&v,   g_v);
    cudaGetSymbolAddress((void**)&o,   g_o);
    cudaGetSymbolAddress((void**)&x1,  g_x1);
    cudaGetSymbolAddress((void**)&xn1, g_xn1);
    cudaGetSymbolAddress((void**)&h1,  g_h1);
    cudaGetSymbolAddress((void**)&moe, g_moe);
    cudaGetSymbolAddress((void**)&x2,  g_x2);
    cudaGetSymbolAddress((void**)&x3,  g_x3);
    cudaGetSymbolAddress((void**)&x4,  g_x4);
    cudaGetSymbolAddress((void**)&wdense, g_wdense);
    cudaGetSymbolAddress((void**)&varbuf, g_var);

    const int SD = kS * kD;

    cudaFuncSetAttribute(gemm_mma, cudaFuncAttributeMaxDynamicSharedMemorySize, GEMM_SMEM);

    // embed (tf32-rounded)
    embed_kernel<<<SD / 256, 256>>>(tokens, emb, x0);

    // qkv projections (weights rounded in-register inside gemm)
    dim3 gDD(kS / 128, kD / 128);
    gemm_mma<<<gDD, 256, GEMM_SMEM>>>(x0, wq, q, kS, kD, kD, nullptr, 0, 0, nullptr, 0);
    gemm_mma<<<gDD, 256, GEMM_SMEM>>>(x0, wk, k, kS, kD, kD, nullptr, 0, 0, nullptr, 0);
    gemm_mma<<<gDD, 256, GEMM_SMEM>>>(x0, wv, v, kS, kD, kD, nullptr, 0, 0, nullptr, 0);

    // rope
    rope_kernel<<<(kS * kH * 32) / 256, 256>>>(q);
    rope_kernel<<<(kS * kH * 32) / 256, 256>>>(k);

    // attention
    int attn_smem = (3 * 64 * 68 + 64) * (int)sizeof(float);
    cudaFuncSetAttribute(attn_kernel, cudaFuncAttributeMaxDynamicSharedMemorySize, attn_smem);
    attn_kernel<<<dim3(kS / 64, kH), 256, attn_smem>>>(q, k, v, o);

    // output projection fused with residual add -> x1
    gemm_mma<<<gDD, 256, GEMM_SMEM>>>(o, wo, x1, kS, kD, kD, nullptr, 0, 0, x0, 1);

    // ln1 (rounded: feeds MoE GEMMs)
    ln_kernel<<<kS, 256>>>(x1, ln1_g, ln1_b, xn1, 1);

    // gate + aux
    gate_kernel<<<kS, 128>>>(xn1, gate_w, wdense, varbuf);
    aux_kernel<<<1, 256>>>(varbuf, out + (size_t)out_size - 1);

    // MoE experts (h3 gemm fuses silu: h1 <- rna(silu(h1)*h3))
    dim3 gFD(kS / 128, kF / 128);
    dim3 gDF(kS / 128, kD / 128);
    for (int e = 0; e < kNE; e++) {
        const float* w1e = w1 + (size_t)e * kF * kD;
        const float* w3e = w3 + (size_t)e * kF * kD;
        const float* w2e = w2 + (size_t)e * kD * kF;
        gemm_mma<<<gFD, 256, GEMM_SMEM>>>(xn1, w1e, h1, kS, kF, kD, nullptr, 0, 0, nullptr, 0);
        gemm_mma<<<gFD, 256, GEMM_SMEM>>>(xn1, w3e, h1, kS, kF, kD, nullptr, 0, 0, h1, 2);
        gemm_mma<<<gDF, 256, GEMM_SMEM>>>(h1, w2e, moe, kS, kD, kF, wdense + e, 4, e ? 1 : 0, nullptr, 0);
    }

    // residual + ln2 + final ln (rounded: feeds head GEMM)
    add_kernel<<<(SD + 255) / 256, 256>>>(moe, xn1, x2, SD);
    ln_kernel<<<kS, 256>>>(x2, ln2_g, ln2_b, x3, 0);
    ln_kernel<<<kS, 256>>>(x3, fin_g, fin_b, x4, 1);

    // LM head
    dim3 gHead(kS / 128, (kVOC + 127) / 128);
    gemm_mma<<<gHead, 256, GEMM_SMEM>>>(x4, head_w, out, kS, kVOC, kD, nullptr, 0, 0, nullptr, 0);
}

// round 5
// speedup vs baseline: 4.8775x; 1.0649x over previous
#include <cuda_runtime.h>
#include <math.h>
#include <stdint.h>

// ---------------- constants ----------------
#define kS   1024
#define kD   2048
#define kH   32
#define kHD  64
#define kF   8192
#define kNE  4
#define kVOC 50257

// ---------------- scratch ----------------
__device__ float g_x0 [kS*kD];
__device__ float g_qkv[kS*3*kD];
__device__ float g_o  [kS*kD];
__device__ float g_x1 [kS*kD];
__device__ float g_xn1[kS*kD];
__device__ float g_ha [kS*kNE*kF];   // w1 outputs, packed [m][e*8192+f]
__device__ float g_hb [kS*kNE*kF];   // A' = wd*silu(h1)*h3, packed
__device__ float g_part[2*kS*kD];    // split-K partials for w2
__device__ float g_x2 [kS*kD];
__device__ float g_x4 [kS*kD];
__device__ float g_wdense[kS*kNE];
__device__ float g_var[kS];

// ---------------- PTX helpers (base sm_103: no tcgen05) ----------------
__device__ __forceinline__ uint32_t smem_u32(const void* p) {
    uint32_t a;
    asm("{ .reg .u64 t; cvta.to.shared.u64 t, %1; cvt.u32.u64 %0, t; }" : "=r"(a) : "l"(p));
    return a;
}
__device__ __forceinline__ float rna_tf32(float x) {
    uint32_t y;
    asm("cvt.rna.tf32.f32 %0, %1;" : "=r"(y) : "f"(x));
    return __uint_as_float(y);
}
__device__ __forceinline__ uint32_t rna_tf32_bits(uint32_t x) {
    uint32_t y;
    asm("cvt.rna.tf32.f32 %0, %1;" : "=r"(y) : "f"(__uint_as_float(x)));
    return y;
}
__device__ __forceinline__ void cpa16(uint32_t dst, const void* src) {
    asm volatile("cp.async.cg.shared.global [%0], [%1], 16;" :: "r"(dst), "l"(src));
}
#define CPA_COMMIT() asm volatile("cp.async.commit_group;" ::: "memory")
#define CPA_WAIT1()  asm volatile("cp.async.wait_group 1;" ::: "memory")

#define LDSM_X4(r, addr) \
    asm volatile("ldmatrix.sync.aligned.m8n8.x4.shared.b16 {%0,%1,%2,%3}, [%4];" \
        : "=r"((r)[0]), "=r"((r)[1]), "=r"((r)[2]), "=r"((r)[3]) : "r"(addr))

__device__ __forceinline__ void mma_tf32(float* c, const uint32_t* a, uint32_t b0, uint32_t b1) {
    asm volatile("mma.sync.aligned.m16n8k8.row.col.f32.tf32.tf32.f32 "
        "{%0,%1,%2,%3}, {%4,%5,%6,%7}, {%8,%9}, {%0,%1,%2,%3};"
        : "+f"(c[0]), "+f"(c[1]), "+f"(c[2]), "+f"(c[3])
        : "r"(a[0]), "r"(a[1]), "r"(a[2]), "r"(a[3]), "r"(b0), "r"(b1));
}

// ---------------- tf32 mma.sync NT GEMM (multi-segment B, split-K, fused epilogues) ---
// C[m,n] (+= over split-K partial buffers) = sum_k A[m,k]*B(n,k)
// B segment select: nShift (segment along n) or kShift>=0 (segment along k-tiles).
// fmode 1: += F[m,n]
// fmode 2: C = rna_tf32( wdense[m, n>>13] * silu(F[m,n]) * acc )
#define BM 128
#define BN 128
#define BK 32
#define NST 3
#define ASTG 16384
#define STG  32768
#define GEMM_SMEM (NST*STG)

__global__ void __launch_bounds__(256, 2) gemm_mma(
    const float* __restrict__ A,
    const float* __restrict__ B0, const float* __restrict__ B1,
    const float* __restrict__ B2, const float* __restrict__ B3,
    float* __restrict__ C,
    int N, int KT, int ldA, int ldB, int ldC,
    int nShift, int kShift, int ktPerZ, long long zStrideC,
    int fmode, const float* __restrict__ F, int ldF,
    const float* __restrict__ wdense)
{
    extern __shared__ char smraw[];
    uint32_t sb = smem_u32(smraw);
    int tid = threadIdx.x, lane = tid & 31, wid = tid >> 5;
    int wm = wid >> 2, wn = wid & 3;
    int bm = blockIdx.x * BM, bn = blockIdx.y * BN;

    C += (long long)blockIdx.z * zStrideC;
    int ktBeg = blockIdx.z * ktPerZ;
    int KTz = KT - ktBeg; if (KTz > ktPerZ) KTz = ktPerZ;

    // n-segment B base (valid when kShift < 0)
    const float* BnBase;
    {
        int seg = bn >> nShift;
        const float* bp = (seg == 0) ? B0 : (seg == 1) ? B1 : (seg == 2) ? B2 : B3;
        BnBase = bp + (size_t)(bn - (seg << nShift)) * ldB;
    }

    auto load_stage = [&](int s, int kt) {
        int ktl = kt;
        const float* Bb = BnBase;
        if (kShift >= 0) {
            int seg = kt >> kShift;
            const float* bp = (seg == 0) ? B0 : (seg == 1) ? B1 : (seg == 2) ? B2 : B3;
            ktl = kt - (seg << kShift);
            Bb = bp + (size_t)bn * ldB;
        }
#pragma unroll
        for (int j = 0; j < 4; j++) {
            int idx = tid + j * 256;
            int row = idx >> 3, c4 = idx & 7;
            uint32_t sw = ((uint32_t)(c4 ^ (row & 7))) << 4;
            uint32_t base = sb + (uint32_t)s * STG + (uint32_t)(row << 7) + sw;
            cpa16(base, A + (size_t)(bm + row) * ldA + kt * BK + c4 * 4);
            if (bn + row < N)
                cpa16(base + ASTG, Bb + (size_t)row * ldB + ktl * BK + c4 * 4);
        }
    };

    float acc[4][4][4];
#pragma unroll
    for (int i = 0; i < 4; i++)
#pragma unroll
        for (int j = 0; j < 4; j++)
#pragma unroll
            for (int r = 0; r < 4; r++) acc[i][j][r] = 0.0f;

    int arow = lane & 15;
    int ahalf = lane >> 4;
    int ars = arow & 7;
    int brow = lane & 7;
    int bq = lane >> 3;
    uint32_t aBase = sb + (uint32_t)((wm * 64 + arow) << 7);
    uint32_t bBase = sb + ASTG + (uint32_t)((wn * 32 + brow) << 7);

#pragma unroll
    for (int s = 0; s < NST - 1; s++) {
        if (s < KTz) load_stage(s, ktBeg + s);
        CPA_COMMIT();
    }

    int scomp = 0, sload = NST - 1;
    for (int t = 0; t < KTz; t++) {
        CPA_WAIT1();
        __syncthreads();
        int tn = t + NST - 1;
        if (tn < KTz) load_stage(sload, ktBeg + tn);
        CPA_COMMIT();

        uint32_t aS = aBase + (uint32_t)scomp * STG;
        uint32_t bS = bBase + (uint32_t)scomp * STG;
#pragma unroll
        for (int kp = 0; kp < 2; kp++) {
            uint32_t bf[4][4];
            uint32_t a0[4][4], a1[4][4];
#pragma unroll
            for (int nt = 0; nt < 4; nt++)
                LDSM_X4(bf[nt], bS + (uint32_t)(nt * 8 * 128) +
                                 ((uint32_t)((kp * 4 + bq) ^ brow) << 4));
#pragma unroll
            for (int mt = 0; mt < 4; mt++)
                LDSM_X4(a0[mt], aS + (uint32_t)(mt * 16 * 128) +
                                 ((uint32_t)(((kp * 2) * 2 + ahalf) ^ ars) << 4));
#pragma unroll
            for (int mt = 0; mt < 4; mt++)
                LDSM_X4(a1[mt], aS + (uint32_t)(mt * 16 * 128) +
                                 ((uint32_t)(((kp * 2 + 1) * 2 + ahalf) ^ ars) << 4));
#pragma unroll
            for (int nt = 0; nt < 4; nt++)
#pragma unroll
                for (int r = 0; r < 4; r++) bf[nt][r] = rna_tf32_bits(bf[nt][r]);
#pragma unroll
            for (int mt = 0; mt < 4; mt++)
#pragma unroll
                for (int nt = 0; nt < 4; nt++)
                    mma_tf32(acc[mt][nt], a0[mt], bf[nt][0], bf[nt][1]);
#pragma unroll
            for (int mt = 0; mt < 4; mt++)
#pragma unroll
                for (int nt = 0; nt < 4; nt++)
                    mma_tf32(acc[mt][nt], a1[mt], bf[nt][2], bf[nt][3]);
        }
        scomp = (scomp + 1 == NST) ? 0 : scomp + 1;
        sload = (sload + 1 == NST) ? 0 : sload + 1;
    }

    // epilogue
    int evenN = ((N & 1) == 0);
#pragma unroll
    for (int mt = 0; mt < 4; mt++) {
        int r0 = bm + wm * 64 + mt * 16 + (lane >> 2);
        int r1 = r0 + 8;
#pragma unroll
        for (int nt = 0; nt < 4; nt++) {
            int n0 = bn + wn * 32 + nt * 8 + 2 * (lane & 3);
            const float* a = acc[mt][nt];
            if (evenN && n0 + 1 < N) {
                size_t i0 = (size_t)r0 * ldC + n0, i1 = (size_t)r1 * ldC + n0;
                float2 v0 = make_float2(a[0], a[1]);
                float2 v1 = make_float2(a[2], a[3]);
                if (fmode == 1) {
                    float2 f0 = *(const float2*)(F + (size_t)r0 * ldF + n0);
                    float2 f1 = *(const float2*)(F + (size_t)r1 * ldF + n0);
                    v0.x += f0.x; v0.y += f0.y; v1.x += f1.x; v1.y += f1.y;
                } else if (fmode == 2) {
                    float2 f0 = *(const float2*)(F + (size_t)r0 * ldF + n0);
                    float2 f1 = *(const float2*)(F + (size_t)r1 * ldF + n0);
                    int e = n0 >> 13;
                    float w0 = wdense[r0 * 4 + e], w1_ = wdense[r1 * 4 + e];
                    v0.x = rna_tf32(w0 * (f0.x / (1.0f + expf(-f0.x))) * v0.x);
                    v0.y = rna_tf32(w0 * (f0.y / (1.0f + expf(-f0.y))) * v0.y);
                    v1.x = rna_tf32(w1_ * (f1.x / (1.0f + expf(-f1.x))) * v1.x);
                    v1.y = rna_tf32(w1_ * (f1.y / (1.0f + expf(-f1.y))) * v1.y);
                }
                *(float2*)(C + i0) = v0;
                *(float2*)(C + i1) = v1;
            } else {
#pragma unroll
                for (int e2 = 0; e2 < 2; e2++) {
                    int nn = n0 + e2;
                    if (nn < N) {
                        size_t i0 = (size_t)r0 * ldC + nn, i1 = (size_t)r1 * ldC + nn;
                        float v0 = a[e2], v1 = a[2 + e2];
                        if (fmode == 1) {
                            v0 += F[(size_t)r0 * ldF + nn];
                            v1 += F[(size_t)r1 * ldF + nn];
                        } else if (fmode == 2) {
                            float f0 = F[(size_t)r0 * ldF + nn], f1 = F[(size_t)r1 * ldF + nn];
                            int e = nn >> 13;
                            v0 = rna_tf32(wdense[r0 * 4 + e] * (f0 / (1.0f + expf(-f0))) * v0);
                            v1 = rna_tf32(wdense[r1 * 4 + e] * (f1 / (1.0f + expf(-f1))) * v1);
                        }
                        C[i0] = v0; C[i1] = v1;
                    }
                }
            }
        }
    }
}

// ---------------- embed ----------------
__global__ void embed_kernel(const int* __restrict__ tok, const float* __restrict__ emb,
                             float* __restrict__ X) {
    int i = blockIdx.x * blockDim.x + threadIdx.x;
    int t = i >> 11;
    int d = i & 2047;
    X[i] = rna_tf32(emb[(size_t)tok[t] * kD + d]);
}

// ---------------- RoPE on packed QKV (q & k halves), in-place ----------------
__global__ void rope_kernel(float* __restrict__ X) {
    int i = blockIdx.x * blockDim.x + threadIdx.x;   // [0, 2*kS*kH*32)
    int sel = i & 1;
    int j = i >> 1;
    int p = j & 31;
    int h = (j >> 5) & 31;
    int t = j >> 10;
    float inv = 1.0f / powf(10000.0f, (float)(2 * p) / 64.0f);
    float ang = (float)t * inv;
    float c = cosf(ang), s = sinf(ang);
    size_t base = (size_t)t * (3 * kD) + sel * kD + h * kHD + 2 * p;
    float x0 = X[base], x1 = X[base + 1];
    X[base]     = x0 * c - x1 * s;
    X[base + 1] = x0 * s + x1 * c;
}

// ---------------- attention (fp32, per-j-block-max exp, matches reference) ----------------
__global__ void attn_kernel(const float* __restrict__ QKV, float* __restrict__ O) {
    extern __shared__ float sm[];
    const int LD = 68;
    const int ldx = 3 * kD;
    float* Qt  = sm;
    float* KP  = Qt + 64 * LD;
    float* Vs  = KP + 64 * LD;
    float* den = Vs + 64 * LD;
    int qi = blockIdx.x;
    int h  = blockIdx.y;
    int tid = threadIdx.x;
    int tx = tid & 15, ty = tid >> 4;
    const float* Q = QKV;
    const float* K = QKV + kD;
    const float* V = QKV + 2 * kD;

    for (int it = tid; it < 1024; it += 256) {
        int q = it >> 4;
        int d4 = (it & 15) << 2;
        float4 vq = *(const float4*)(Q + (size_t)(qi * 64 + q) * ldx + h * kHD + d4);
        Qt[(d4 + 0) * LD + q] = vq.x;
        Qt[(d4 + 1) * LD + q] = vq.y;
        Qt[(d4 + 2) * LD + q] = vq.z;
        Qt[(d4 + 3) * LD + q] = vq.w;
    }
    if (tid < 64) den[tid] = 0.0f;

    float o[4][4] = {};
    for (int j = 0; j <= qi; j++) {
        __syncthreads();
        for (int it = tid; it < 1024; it += 256) {
            int r = it >> 4;
            int d4 = (it & 15) << 2;
            float4 kv = *(const float4*)(K + (size_t)(j * 64 + r) * ldx + h * kHD + d4);
            KP[(d4 + 0) * LD + r] = kv.x;
            KP[(d4 + 1) * LD + r] = kv.y;
            KP[(d4 + 2) * LD + r] = kv.z;
            KP[(d4 + 3) * LD + r] = kv.w;
            float4 vv = *(const float4*)(V + (size_t)(j * 64 + r) * ldx + h * kHD + d4);
            *(float4*)&Vs[r * LD + d4] = vv;
        }
        __syncthreads();
        float s[4][4] = {};
#pragma unroll 8
        for (int d = 0; d < 64; d++) {
            float4 a = *(const float4*)&Qt[d * LD + (ty << 2)];
            float4 b = *(const float4*)&KP[d * LD + (tx << 2)];
            float av[4] = {a.x, a.y, a.z, a.w};
            float bv[4] = {b.x, b.y, b.z, b.w};
#pragma unroll
            for (int i = 0; i < 4; i++)
#pragma unroll
                for (int j2 = 0; j2 < 4; j2++) s[i][j2] += av[i] * bv[j2];
        }
        __syncthreads();
#pragma unroll
        for (int i = 0; i < 4; i++) {
#pragma unroll
            for (int j2 = 0; j2 < 4; j2++) {
                int q = ty * 4 + i;
                int kcol = tx * 4 + j2;
                float val = s[i][j2] * 0.125f;
                if (j == qi && kcol > q) val = -INFINITY;
                KP[kcol * LD + q] = val;
            }
        }
        __syncthreads();
        if (tid < 64) {
            float m = -INFINITY;
            for (int k2 = 0; k2 < 64; k2++) m = fmaxf(m, KP[k2 * LD + tid]);
            float ds = 0.0f;
            for (int k2 = 0; k2 < 64; k2++) {
                float pexp = expf(KP[k2 * LD + tid] - m);
                KP[k2 * LD + tid] = pexp;
                ds += pexp;
            }
            den[tid] += ds;
        }
        __syncthreads();
#pragma unroll 8
        for (int k2 = 0; k2 < 64; k2++) {
            float4 a = *(const float4*)&KP[k2 * LD + (ty << 2)];
            float4 b = *(const float4*)&Vs[k2 * LD + (tx << 2)];
            float av[4] = {a.x, a.y, a.z, a.w};
            float bv[4] = {b.x, b.y, b.z, b.w};
#pragma unroll
            for (int i = 0; i < 4; i++)
#pragma unroll
                for (int j2 = 0; j2 < 4; j2++) o[i][j2] += av[i] * bv[j2];
        }
    }
    __syncthreads();
#pragma unroll
    for (int i = 0; i < 4; i++) {
        int q = ty * 4 + i;
        float dn = den[q] + 1e-6f;
#pragma unroll
        for (int j2 = 0; j2 < 4; j2++) {
            int d = tx * 4 + j2;
            O[(size_t)(qi * 64 + q) * kD + h * kHD + d] = rna_tf32(o[i][j2] / dn);
        }
    }
}

// ---------------- reduce: x2 = p0 + p1 + xn1 ----------------
__global__ void reduce_kernel(const float* __restrict__ P, const float* __restrict__ R,
                              float* __restrict__ Y, int n) {
    int i = blockIdx.x * blockDim.x + threadIdx.x;
    if (i < n) Y[i] = P[i] + P[(size_t)n + i] + R[i];
}

// ---------------- layernorm ----------------
__global__ void ln_kernel(const float* __restrict__ X, const float* __restrict__ g,
                          const float* __restrict__ b, float* __restrict__ Y, int doRound) {
    int row = blockIdx.x;
    int tid = threadIdx.x;
    __shared__ float red[256];
    __shared__ float s_mu, s_inv;
    const float* x = X + (size_t)row * kD;
    float s = 0.0f;
    for (int i = tid; i < kD; i += 256) s += x[i];
    red[tid] = s; __syncthreads();
    for (int st = 128; st > 0; st >>= 1) { if (tid < st) red[tid] += red[tid + st]; __syncthreads(); }
    if (tid == 0) s_mu = red[0] / (float)kD;
    __syncthreads();
    float mu = s_mu;
    float v = 0.0f;
    for (int i = tid; i < kD; i += 256) { float d = x[i] - mu; v += d * d; }
    red[tid] = v; __syncthreads();
    for (int st = 128; st > 0; st >>= 1) { if (tid < st) red[tid] += red[tid + st]; __syncthreads(); }
    if (tid == 0) s_inv = 1.0f / sqrtf(red[0] / (float)kD + 1e-5f);
    __syncthreads();
    float inv = s_inv;
    for (int i = tid; i < kD; i += 256) {
        float y = (x[i] - mu) * inv * g[i] + b[i];
        Y[(size_t)row * kD + i] = doRound ? rna_tf32(y) : y;
    }
}

// ---------------- fused double layernorm (ln2 then final ln), rounded output ----------------
__global__ void ln2x_kernel(const float* __restrict__ X,
                            const float* __restrict__ g2, const float* __restrict__ b2,
                            const float* __restrict__ gf, const float* __restrict__ bf,
                            float* __restrict__ Y) {
    int row = blockIdx.x;
    int tid = threadIdx.x;
    __shared__ float red[256];
    __shared__ float s_mu, s_inv;
    __shared__ float buf[kD];
    const float* x = X + (size_t)row * kD;
    // LN pass 1
    float s = 0.0f;
    for (int i = tid; i < kD; i += 256) s += x[i];
    red[tid] = s; __syncthreads();
    for (int st = 128; st > 0; st >>= 1) { if (tid < st) red[tid] += red[tid + st]; __syncthreads(); }
    if (tid == 0) s_mu = red[0] / (float)kD;
    __syncthreads();
    float mu = s_mu;
    float v = 0.0f;
    for (int i = tid; i < kD; i += 256) { float d = x[i] - mu; v += d * d; }
    red[tid] = v; __syncthreads();
    for (int st = 128; st > 0; st >>= 1) { if (tid < st) red[tid] += red[tid + st]; __syncthreads(); }
    if (tid == 0) s_inv = 1.0f / sqrtf(red[0] / (float)kD + 1e-5f);
    __syncthreads();
    float inv = s_inv;
    for (int i = tid; i < kD; i += 256)
        buf[i] = (x[i] - mu) * inv * g2[i] + b2[i];
    __syncthreads();
    // LN pass 2 on buf
    s = 0.0f;
    for (int i = tid; i < kD; i += 256) s += buf[i];
    red[tid] = s; __syncthreads();
    for (int st = 128; st > 0; st >>= 1) { if (tid < st) red[tid] += red[tid + st]; __syncthreads(); }
    if (tid == 0) s_mu = red[0] / (float)kD;
    __syncthreads();
    mu = s_mu;
    v = 0.0f;
    for (int i = tid; i < kD; i += 256) { float d = buf[i] - mu; v += d * d; }
    red[tid] = v; __syncthreads();
    for (int st = 128; st > 0; st >>= 1) { if (tid < st) red[tid] += red[tid + st]; __syncthreads(); }
    if (tid == 0) s_inv = 1.0f / sqrtf(red[0] / (float)kD + 1e-5f);
    __syncthreads();
    inv = s_inv;
    for (int i = tid; i < kD; i += 256)
        Y[(size_t)row * kD + i] = rna_tf32((buf[i] - mu) * inv * gf[i] + bf[i]);
}

// ---------------- gate ----------------
__global__ void gate_kernel(const float* __restrict__ X, const float* __restrict__ GW,
                            float* __restrict__ wdense, float* __restrict__ varbuf) {
    int t = blockIdx.x;
    int tid = threadIdx.x;
    __shared__ float red[128];
    __shared__ float logits[4];
    const float* x = X + (size_t)t * kD;
    float acc[4] = {0.f, 0.f, 0.f, 0.f};
    for (int d = tid; d < kD; d += 128) {
        float xv = x[d];
        acc[0] += xv * GW[0 * kD + d];
        acc[1] += xv * GW[1 * kD + d];
        acc[2] += xv * GW[2 * kD + d];
        acc[3] += xv * GW[3 * kD + d];
    }
    for (int e = 0; e < 4; e++) {
        red[tid] = acc[e]; __syncthreads();
        for (int st = 64; st > 0; st >>= 1) { if (tid < st) red[tid] += red[tid + st]; __syncthreads(); }
        if (tid == 0) logits[e] = red[0];
        __syncthreads();
    }
    if (tid == 0) {
        float l[4] = {logits[0], logits[1], logits[2], logits[3]};
        float mx = fmaxf(fmaxf(l[0], l[1]), fmaxf(l[2], l[3]));
        float pe[4], ps = 0.f;
        for (int e = 0; e < 4; e++) { pe[e] = expf(l[e] - mx); ps += pe[e]; }
        float pr[4];
        for (int e = 0; e < 4; e++) pr[e] = pe[e] / ps;
        int a = 0;
        for (int e = 1; e < 4; e++) if (pr[e] > pr[a]) a = e;
        int b2 = -1;
        for (int e = 0; e < 4; e++) { if (e == a) continue; if (b2 < 0 || pr[e] > pr[b2]) b2 = e; }
        float wsum = pr[a] + pr[b2];
        float w[4] = {0.f, 0.f, 0.f, 0.f};
        w[a] = pr[a] / wsum; w[b2] = pr[b2] / wsum;
        for (int e = 0; e < 4; e++) wdense[t * 4 + e] = w[e];
        float mu = 0.25f * (l[0] + l[1] + l[2] + l[3]);
        float vv = 0.f;
        for (int e = 0; e < 4; e++) { float d = l[e] - mu; vv += d * d; }
        varbuf[t] = vv / 3.0f;
    }
}

__global__ void aux_kernel(const float* __restrict__ varbuf, float* __restrict__ out) {
    __shared__ float red[256];
    int tid = threadIdx.x;
    float s = 0.f;
    for (int i = tid; i < kS; i += 256) s += varbuf[i];
    red[tid] = s; __syncthreads();
    for (int st = 128; st > 0; st >>= 1) { if (tid < st) red[tid] += red[tid + st]; __syncthreads(); }
    if (tid == 0) out[0] = red[0] / (float)kS;
}

// ---------------- launch ----------------
extern "C" void kernel_launch(void* const* d_in, const int* in_sizes, int n_in,
                              void* d_out, int out_size) {
    const int*   tokens = (const int*)d_in[0];
    const float* emb    = (const float*)d_in[1];
    const float* wq     = (const float*)d_in[2];
    const float* wk     = (const float*)d_in[3];
    const float* wv     = (const float*)d_in[4];
    const float* wo     = (const float*)d_in[5];
    const float* ln1_g  = (const float*)d_in[6];
    const float* ln1_b  = (const float*)d_in[7];
    const float* gate_w = (const float*)d_in[8];
    const float* w1     = (const float*)d_in[9];
    const float* w2     = (const float*)d_in[10];
    const float* w3     = (const float*)d_in[11];
    const float* ln2_g  = (const float*)d_in[12];
    const float* ln2_b  = (const float*)d_in[13];
    const float* fin_g  = (const float*)d_in[14];
    const float* fin_b  = (const float*)d_in[15];
    const float* head_w = (const float*)d_in[16];
    float* out = (float*)d_out;

    float *x0, *qkv, *o, *x1, *xn1, *ha, *hb, *part, *x2, *x4, *wdense, *varbuf;
    cudaGetSymbolAddress((void**)&x0,  g_x0);
    cudaGetSymbolAddress((void**)&qkv, g_qkv);
    cudaGetSymbolAddress((void**)&o,   g_o);
    cudaGetSymbolAddress((void**)&x1,  g_x1);
    cudaGetSymbolAddress((void**)&xn1, g_xn1);
    cudaGetSymbolAddress((void**)&ha,  g_ha);
    cudaGetSymbolAddress((void**)&hb,  g_hb);
    cudaGetSymbolAddress((void**)&part, g_part);
    cudaGetSymbolAddress((void**)&x2,  g_x2);
    cudaGetSymbolAddress((void**)&x4,  g_x4);
    cudaGetSymbolAddress((void**)&wdense, g_wdense);
    cudaGetSymbolAddress((void**)&varbuf, g_var);

    const int SD = kS * kD;
    const int KFD = kF * kD;

    cudaFuncSetAttribute(gemm_mma, cudaFuncAttributeMaxDynamicSharedMemorySize, GEMM_SMEM);

    // embed (tf32-rounded)
    embed_kernel<<<SD / 256, 256>>>(tokens, emb, x0);

    // fused QKV projection -> packed g_qkv [1024][6144]
    gemm_mma<<<dim3(kS / 128, 48), 256, GEMM_SMEM>>>(
        x0, wq, wk, wv, nullptr, qkv,
        3 * kD, kD / BK, kD, kD, 3 * kD,
        /*nShift=*/11, /*kShift=*/-1, /*ktPerZ=*/kD / BK, 0,
        0, nullptr, 0, nullptr);

    // rope on q & k halves of packed buffer
    rope_kernel<<<(2 * kS * kH * 32) / 256, 256>>>(qkv);

    // attention
    int attn_smem = (3 * 64 * 68 + 64) * (int)sizeof(float);
    cudaFuncSetAttribute(attn_kernel, cudaFuncAttributeMaxDynamicSharedMemorySize, attn_smem);
    attn_kernel<<<dim3(kS / 64, kH), 256, attn_smem>>>(qkv, o);

    // output projection fused with residual add -> x1
    gemm_mma<<<dim3(kS / 128, kD / 128), 256, GEMM_SMEM>>>(
        o, wo, nullptr, nullptr, nullptr, x1,
        kD, kD / BK, kD, kD, kD,
        30, -1, kD / BK, 0,
        1, x0, kD, nullptr);

    // ln1 (rounded: feeds MoE + gate)
    ln_kernel<<<kS, 256>>>(x1, ln1_g, ln1_b, xn1, 1);

    // gate + aux
    gate_kernel<<<kS, 128>>>(xn1, gate_w, wdense, varbuf);
    aux_kernel<<<1, 256>>>(varbuf, out + (size_t)out_size - 1);

    // MoE: all-expert w1 -> ha (raw fp32)
    gemm_mma<<<dim3(kS / 128, 256), 256, GEMM_SMEM>>>(
        xn1, w1 + 0 * (size_t)KFD, w1 + 1 * (size_t)KFD, w1 + 2 * (size_t)KFD, w1 + 3 * (size_t)KFD,
        ha, kNE * kF, kD / BK, kD, kD, kNE * kF,
        13, -1, kD / BK, 0,
        0, nullptr, 0, nullptr);

    // all-expert w3 with fused gating epilogue -> hb = rna(wd * silu(ha) * acc)
    gemm_mma<<<dim3(kS / 128, 256), 256, GEMM_SMEM>>>(
        xn1, w3 + 0 * (size_t)KFD, w3 + 1 * (size_t)KFD, w3 + 2 * (size_t)KFD, w3 + 3 * (size_t)KFD,
        hb, kNE * kF, kD / BK, kD, kD, kNE * kF,
        13, -1, kD / BK, 0,
        2, ha, kNE * kF, wdense);

    // fused 4-expert w2 with K=32768, split-K=2 -> partials
    gemm_mma<<<dim3(kS / 128, kD / 128, 2), 256, GEMM_SMEM>>>(
        hb, w2 + 0 * (size_t)KFD, w2 + 1 * (size_t)KFD, w2 + 2 * (size_t)KFD, w2 + 3 * (size_t)KFD,
        part, kD, (kNE * kF) / BK, kNE * kF, kF, kD,
        30, /*kShift=*/8, /*ktPerZ=*/(kNE * kF) / BK / 2, (long long)SD,
        0, nullptr, 0, nullptr);

    // reduce partials + residual -> x2
    reduce_kernel<<<(SD + 255) / 256, 256>>>(part, xn1, x2, SD);

    // ln2 + final ln fused (rounded: feeds head GEMM)
    ln2x_kernel<<<kS, 256>>>(x2, ln2_g, ln2_b, fin_g, fin_b, x4);

    // LM head
    gemm_mma<<<dim3(kS / 128, (kVOC + 127) / 128), 256, GEMM_SMEM>>>(
        x4, head_w, nullptr, nullptr, nullptr, out,
        kVOC, kD / BK, kD, kD, kVOC,
        30, -1, kD / BK, 0,
        0, nullptr, 0, nullptr);
}

// round 6
// speedup vs baseline: 7.7616x; 1.5913x over previous
#include <cuda_runtime.h>
#include <cuda_fp16.h>
#include <math.h>
#include <stdint.h>

// ---------------- constants ----------------
#define kS   1024
#define kD   2048
#define kH   32
#define kHD  64
#define kF   8192
#define kNE  4
#define kVOC 50257

// ---------------- scratch ----------------
// half weights
__device__ __half g_wqh[kD*kD];
__device__ __half g_wkh[kD*kD];
__device__ __half g_wvh[kD*kD];
__device__ __half g_woh[kD*kD];
__device__ __half g_w1h[kNE*kF*kD];
__device__ __half g_w3h[kNE*kF*kD];
__device__ __half g_w2h[kNE*kD*kF];
__device__ __half g_hdh[kVOC*kD];
// half activations
__device__ __half g_x0h [kS*kD];
__device__ __half g_qkvh[kS*3*kD];
__device__ __half g_oh  [kS*kD];
__device__ __half g_xn1h[kS*kD];
__device__ __half g_hah [kS*kNE*kF];
__device__ __half g_hbh [kS*kNE*kF];
__device__ __half g_x4h [kS*kD];
// fp32
__device__ float g_part[2*kS*3*kD];
__device__ float g_x1 [kS*kD];
__device__ float g_x2 [kS*kD];
__device__ float g_wdense[kS*kNE];
__device__ float g_var[kS];

// ---------------- PTX helpers ----------------
__device__ __forceinline__ uint32_t smem_u32(const void* p) {
    uint32_t a;
    asm("{ .reg .u64 t; cvta.to.shared.u64 t, %1; cvt.u32.u64 %0, t; }" : "=r"(a) : "l"(p));
    return a;
}
__device__ __forceinline__ void cpa16(uint32_t dst, const void* src) {
    asm volatile("cp.async.cg.shared.global [%0], [%1], 16;" :: "r"(dst), "l"(src));
}
#define CPA_COMMIT() asm volatile("cp.async.commit_group;" ::: "memory")
#define CPA_WAIT1()  asm volatile("cp.async.wait_group 1;" ::: "memory")

#define LDSM_X4(r, addr) \
    asm volatile("ldmatrix.sync.aligned.m8n8.x4.shared.b16 {%0,%1,%2,%3}, [%4];" \
        : "=r"((r)[0]), "=r"((r)[1]), "=r"((r)[2]), "=r"((r)[3]) : "r"(addr))

__device__ __forceinline__ void mma_f16(float* c, const uint32_t* a, uint32_t b0, uint32_t b1) {
    asm volatile("mma.sync.aligned.m16n8k16.row.col.f32.f16.f16.f32 "
        "{%0,%1,%2,%3}, {%4,%5,%6,%7}, {%8,%9}, {%0,%1,%2,%3};"
        : "+f"(c[0]), "+f"(c[1]), "+f"(c[2]), "+f"(c[3])
        : "r"(a[0]), "r"(a[1]), "r"(a[2]), "r"(a[3]), "r"(b0), "r"(b1));
}

// ---------------- fp16 mma.sync NT GEMM ----------------
// C[m,n] = sum_k A[m,k]*B(n,k); A,B half, acc fp32.
// B segment select: nShift (along n) or kShift (along 64-k tiles).
// Output: Ch (half) if nonnull else Cf (fp32, split-K via blockIdx.z partials).
// fmode 2: C = half( wdense[m, n>>13] * silu(F[m,n]) * acc )
#define BM 128
#define BN 128
#define BKH 64
#define NSTG 3
#define ASTG 16384
#define STGB 32768
#define GEMM_SMEM (NSTG*STGB)

__global__ void __launch_bounds__(256, 2) gemm_h(
    const __half* __restrict__ A,
    const __half* __restrict__ B0, const __half* __restrict__ B1,
    const __half* __restrict__ B2, const __half* __restrict__ B3,
    float* __restrict__ Cf, __half* __restrict__ Ch,
    int N, int KT, int ldA, int ldB, int ldC,
    int nShift, int kShift, int ktPerZ, long long zStrideC,
    int fmode, const __half* __restrict__ F, int ldF,
    const float* __restrict__ wdense)
{
    extern __shared__ char smraw[];
    uint32_t sb = smem_u32(smraw);
    int tid = threadIdx.x, lane = tid & 31, wid = tid >> 5;
    int wm = wid >> 2, wn = wid & 3;
    int bm = blockIdx.x * BM, bn = blockIdx.y * BN;

    Cf += (long long)blockIdx.z * zStrideC;
    int ktBeg = blockIdx.z * ktPerZ;
    int KTz = KT - ktBeg; if (KTz > ktPerZ) KTz = ktPerZ;

    const __half* BnBase;
    {
        int seg = bn >> nShift;
        const __half* bp = (seg == 0) ? B0 : (seg == 1) ? B1 : (seg == 2) ? B2 : B3;
        BnBase = bp + (size_t)(bn - (seg << nShift)) * ldB;
    }

    auto load_stage = [&](int s, int kt) {
        int ktl = kt;
        const __half* Bb = BnBase;
        if (kShift >= 0) {
            int seg = kt >> kShift;
            const __half* bp = (seg == 0) ? B0 : (seg == 1) ? B1 : (seg == 2) ? B2 : B3;
            ktl = kt - (seg << kShift);
            Bb = bp + (size_t)bn * ldB;
        }
#pragma unroll
        for (int j = 0; j < 8; j++) {
            int idx = tid + j * 256;
            int isB = idx >> 10;
            int un = idx & 1023;
            int row = un >> 3, c = un & 7;
            uint32_t base = sb + (uint32_t)s * STGB + (isB ? ASTG : 0u)
                          + (uint32_t)(row << 7) + ((uint32_t)(c ^ (row & 7)) << 4);
            if (!isB) {
                cpa16(base, A + (size_t)(bm + row) * ldA + kt * BKH + c * 8);
            } else if (bn + row < N) {
                cpa16(base, Bb + (size_t)row * ldB + ktl * BKH + c * 8);
            }
        }
    };

    float acc[4][4][4];
#pragma unroll
    for (int i = 0; i < 4; i++)
#pragma unroll
        for (int j = 0; j < 4; j++)
#pragma unroll
            for (int r = 0; r < 4; r++) acc[i][j][r] = 0.0f;

    // ldmatrix lane geometry (fp16)
    int l7 = lane & 7;
    int sub = lane >> 3;
    int arow = (sub & 1) * 8 + l7;       // A: rows 0-15 pattern
    int ah   = sub >> 1;                 // A: 16B chunk within kstep
    int bnl  = (sub >> 1) * 8 + l7;      // B: n rows 0-15 pattern
    int bch  = sub & 1;                  // B: chunk within kstep
    uint32_t aBase = sb + (uint32_t)((wm * 64 + arow) << 7);
    uint32_t bBase = sb + ASTG + (uint32_t)((wn * 32 + bnl) << 7);

#pragma unroll
    for (int s = 0; s < NSTG - 1; s++) {
        if (s < KTz) load_stage(s, ktBeg + s);
        CPA_COMMIT();
    }

    int scomp = 0, sload = NSTG - 1;
    for (int t = 0; t < KTz; t++) {
        CPA_WAIT1();
        __syncthreads();
        int tn = t + NSTG - 1;
        if (tn < KTz) load_stage(sload, ktBeg + tn);
        CPA_COMMIT();

        uint32_t aS = aBase + (uint32_t)scomp * STGB;
        uint32_t bS = bBase + (uint32_t)scomp * STGB;
#pragma unroll
        for (int ks = 0; ks < 4; ks++) {
            uint32_t bf[2][4];
            uint32_t af[4][4];
#pragma unroll
            for (int ntp = 0; ntp < 2; ntp++)
                LDSM_X4(bf[ntp], bS + (uint32_t)(ntp * 2048) +
                                  ((uint32_t)((2 * ks + bch) ^ l7) << 4));
#pragma unroll
            for (int mt = 0; mt < 4; mt++)
                LDSM_X4(af[mt], aS + (uint32_t)(mt * 2048) +
                                 ((uint32_t)((2 * ks + ah) ^ l7) << 4));
#pragma unroll
            for (int mt = 0; mt < 4; mt++)
#pragma unroll
                for (int nt = 0; nt < 4; nt++)
                    mma_f16(acc[mt][nt], af[mt],
                            bf[nt >> 1][(nt & 1) * 2], bf[nt >> 1][(nt & 1) * 2 + 1]);
        }
        scomp = (scomp + 1 == NSTG) ? 0 : scomp + 1;
        sload = (sload + 1 == NSTG) ? 0 : sload + 1;
    }

    // epilogue
    int evenN = ((N & 1) == 0);
#pragma unroll
    for (int mt = 0; mt < 4; mt++) {
        int r0 = bm + wm * 64 + mt * 16 + (lane >> 2);
        int r1 = r0 + 8;
#pragma unroll
        for (int nt = 0; nt < 4; nt++) {
            int n0 = bn + wn * 32 + nt * 8 + 2 * (lane & 3);
            const float* a = acc[mt][nt];
            float v00 = a[0], v01 = a[1], v10 = a[2], v11 = a[3];
            if (fmode == 2) {
                float2 f0 = __half22float2(*(const __half2*)(F + (size_t)r0 * ldF + n0));
                float2 f1 = __half22float2(*(const __half2*)(F + (size_t)r1 * ldF + n0));
                int e = n0 >> 13;
                float w0 = wdense[r0 * 4 + e], w1_ = wdense[r1 * 4 + e];
                v00 = w0 * (f0.x / (1.0f + __expf(-f0.x))) * v00;
                v01 = w0 * (f0.y / (1.0f + __expf(-f0.y))) * v01;
                v10 = w1_ * (f1.x / (1.0f + __expf(-f1.x))) * v10;
                v11 = w1_ * (f1.y / (1.0f + __expf(-f1.y))) * v11;
            }
            if (Ch) {
                *(__half2*)(Ch + (size_t)r0 * ldC + n0) = __floats2half2_rn(v00, v01);
                *(__half2*)(Ch + (size_t)r1 * ldC + n0) = __floats2half2_rn(v10, v11);
            } else if (evenN && n0 + 1 < N) {
                *(float2*)(Cf + (size_t)r0 * ldC + n0) = make_float2(v00, v01);
                *(float2*)(Cf + (size_t)r1 * ldC + n0) = make_float2(v10, v11);
            } else {
                if (n0 < N)     { Cf[(size_t)r0 * ldC + n0] = v00; Cf[(size_t)r1 * ldC + n0] = v10; }
                if (n0 + 1 < N) { Cf[(size_t)r0 * ldC + n0 + 1] = v01; Cf[(size_t)r1 * ldC + n0 + 1] = v11; }
            }
        }
    }
}

// ---------------- weight convert fp32 -> fp16 ----------------
__global__ void cvt_h(const float* __restrict__ in, __half* __restrict__ out, int n4) {
    int i = blockIdx.x * blockDim.x + threadIdx.x;
    if (i < n4) {
        float4 v = ((const float4*)in)[i];
        __half2 h0 = __floats2half2_rn(v.x, v.y);
        __half2 h1 = __floats2half2_rn(v.z, v.w);
        uint2 pr;
        pr.x = *reinterpret_cast<uint32_t*>(&h0);
        pr.y = *reinterpret_cast<uint32_t*>(&h1);
        ((uint2*)out)[i] = pr;
    }
}

// ---------------- embed (half out) ----------------
__global__ void embed_kernel(const int* __restrict__ tok, const float* __restrict__ emb,
                             __half* __restrict__ X) {
    int i = blockIdx.x * blockDim.x + threadIdx.x;
    int t = i >> 11;
    int d = i & 2047;
    X[i] = __float2half_rn(emb[(size_t)tok[t] * kD + d]);
}

// ---------------- RoPE on packed half QKV ----------------
__global__ void rope_kernel(__half* __restrict__ X) {
    int i = blockIdx.x * blockDim.x + threadIdx.x;   // [0, 2*kS*kH*32)
    int sel = i & 1;
    int j = i >> 1;
    int p = j & 31;
    int h = (j >> 5) & 31;
    int t = j >> 10;
    float inv = 1.0f / powf(10000.0f, (float)(2 * p) / 64.0f);
    float ang = (float)t * inv;
    float c = cosf(ang), s = sinf(ang);
    size_t base = (size_t)t * (3 * kD) + sel * kD + h * kHD + 2 * p;
    __half2* px = (__half2*)(X + base);
    float2 x = __half22float2(*px);
    *px = __floats2half2_rn(x.x * c - x.y * s, x.x * s + x.y * c);
}

// ---------------- attention (fp32 compute, half IO, parallel softmax) ----------------
__global__ void attn_kernel(const __half* __restrict__ QKV, __half* __restrict__ O) {
    extern __shared__ float sm[];
    const int LD = 68;
    const int ldx = 3 * kD;
    float* Qt  = sm;
    float* KP  = Qt + 64 * LD;
    float* Vs  = KP + 64 * LD;
    float* den = Vs + 64 * LD;
    int qi = blockIdx.x;
    int h  = blockIdx.y;
    int tid = threadIdx.x;
    int tx = tid & 15, ty = tid >> 4;

    for (int it = tid; it < 512; it += 256) {
        int q = it >> 3;
        int c8 = (it & 7) << 3;
        uint4 raw = *(const uint4*)(QKV + (size_t)(qi * 64 + q) * ldx + h * kHD + c8);
        const __half2* hp = (const __half2*)&raw;
#pragma unroll
        for (int m = 0; m < 4; m++) {
            float2 f = __half22float2(hp[m]);
            Qt[(c8 + 2 * m) * LD + q] = f.x;
            Qt[(c8 + 2 * m + 1) * LD + q] = f.y;
        }
    }
    if (tid < 64) den[tid] = 0.0f;

    float o[4][4] = {};
    for (int j = 0; j <= qi; j++) {
        __syncthreads();
        for (int it = tid; it < 512; it += 256) {
            int r = it >> 3;
            int c8 = (it & 7) << 3;
            uint4 kraw = *(const uint4*)(QKV + kD + (size_t)(j * 64 + r) * ldx + h * kHD + c8);
            uint4 vraw = *(const uint4*)(QKV + 2 * kD + (size_t)(j * 64 + r) * ldx + h * kHD + c8);
            const __half2* kp = (const __half2*)&kraw;
            const __half2* vp = (const __half2*)&vraw;
#pragma unroll
            for (int m = 0; m < 4; m++) {
                float2 fk = __half22float2(kp[m]);
                KP[(c8 + 2 * m) * LD + r] = fk.x;
                KP[(c8 + 2 * m + 1) * LD + r] = fk.y;
                float2 fv = __half22float2(vp[m]);
                Vs[r * LD + c8 + 2 * m] = fv.x;
                Vs[r * LD + c8 + 2 * m + 1] = fv.y;
            }
        }
        __syncthreads();
        float s[4][4] = {};
#pragma unroll 8
        for (int d = 0; d < 64; d++) {
            float4 a = *(const float4*)&Qt[d * LD + (ty << 2)];
            float4 b = *(const float4*)&KP[d * LD + (tx << 2)];
            float av[4] = {a.x, a.y, a.z, a.w};
            float bv[4] = {b.x, b.y, b.z, b.w};
#pragma unroll
            for (int i = 0; i < 4; i++)
#pragma unroll
                for (int j2 = 0; j2 < 4; j2++) s[i][j2] += av[i] * bv[j2];
        }
        __syncthreads();
#pragma unroll
        for (int i = 0; i < 4; i++) {
#pragma unroll
            for (int j2 = 0; j2 < 4; j2++) {
                int q = ty * 4 + i;
                int kcol = tx * 4 + j2;
                float val = s[i][j2] * 0.125f;
                if (j == qi && kcol > q) val = -INFINITY;
                KP[kcol * LD + q] = val;
            }
        }
        __syncthreads();
        // parallel per-row softmax: 4 threads per row, shfl-reduce
        {
            int q = tid >> 2, part = tid & 3;
            float m = -INFINITY;
#pragma unroll
            for (int i = 0; i < 16; i++)
                m = fmaxf(m, KP[(part + 4 * i) * LD + q]);
            m = fmaxf(m, __shfl_xor_sync(0xFFFFFFFFu, m, 1));
            m = fmaxf(m, __shfl_xor_sync(0xFFFFFFFFu, m, 2));
            float ds = 0.0f;
#pragma unroll
            for (int i = 0; i < 16; i++) {
                int k2 = part + 4 * i;
                float p = __expf(KP[k2 * LD + q] - m);
                KP[k2 * LD + q] = p;
                ds += p;
            }
            ds += __shfl_xor_sync(0xFFFFFFFFu, ds, 1);
            ds += __shfl_xor_sync(0xFFFFFFFFu, ds, 2);
            if (part == 0) den[q] += ds;
        }
        __syncthreads();
#pragma unroll 8
        for (int k2 = 0; k2 < 64; k2++) {
            float4 a = *(const float4*)&KP[k2 * LD + (ty << 2)];
            float4 b = *(const float4*)&Vs[k2 * LD + (tx << 2)];
            float av[4] = {a.x, a.y, a.z, a.w};
            float bv[4] = {b.x, b.y, b.z, b.w};
#pragma unroll
            for (int i = 0; i < 4; i++)
#pragma unroll
                for (int j2 = 0; j2 < 4; j2++) o[i][j2] += av[i] * bv[j2];
        }
    }
    __syncthreads();
#pragma unroll
    for (int i = 0; i < 4; i++) {
        int q = ty * 4 + i;
        float dn = den[q] + 1e-6f;
#pragma unroll
        for (int j2 = 0; j2 < 4; j2++) {
            int d = tx * 4 + j2;
            O[(size_t)(qi * 64 + q) * kD + h * kHD + d] = __float2half_rn(o[i][j2] / dn);
        }
    }
}

// ---------------- split-K reduce: v = P[i] + P[n+i] (+ half residual) ----------------
__global__ void reduce_k(const float* __restrict__ P, const __half* __restrict__ R,
                         float* __restrict__ Cf, __half* __restrict__ Ch, int n) {
    int i = blockIdx.x * blockDim.x + threadIdx.x;
    if (i < n) {
        float v = P[i] + P[(size_t)n + i];
        if (R) v += __half2float(R[i]);
        if (Ch) Ch[i] = __float2half_rn(v);
        else    Cf[i] = v;
    }
}

// ---------------- layernorm (fp32 in, half out) ----------------
__global__ void ln_kernel(const float* __restrict__ X, const float* __restrict__ g,
                          const float* __restrict__ b, __half* __restrict__ Y) {
    int row = blockIdx.x;
    int tid = threadIdx.x;
    __shared__ float red[256];
    __shared__ float s_mu, s_inv;
    const float* x = X + (size_t)row * kD;
    float s = 0.0f;
    for (int i = tid; i < kD; i += 256) s += x[i];
    red[tid] = s; __syncthreads();
    for (int st = 128; st > 0; st >>= 1) { if (tid < st) red[tid] += red[tid + st]; __syncthreads(); }
    if (tid == 0) s_mu = red[0] / (float)kD;
    __syncthreads();
    float mu = s_mu;
    float v = 0.0f;
    for (int i = tid; i < kD; i += 256) { float d = x[i] - mu; v += d * d; }
    red[tid] = v; __syncthreads();
    for (int st = 128; st > 0; st >>= 1) { if (tid < st) red[tid] += red[tid + st]; __syncthreads(); }
    if (tid == 0) s_inv = 1.0f / sqrtf(red[0] / (float)kD + 1e-5f);
    __syncthreads();
    float inv = s_inv;
    for (int i = tid; i < kD; i += 256)
        Y[(size_t)row * kD + i] = __float2half_rn((x[i] - mu) * inv * g[i] + b[i]);
}

// ---------------- fused double layernorm (fp32 in, half out) ----------------
__global__ void ln2x_kernel(const float* __restrict__ X,
                            const float* __restrict__ g2, const float* __restrict__ b2,
                            const float* __restrict__ gf, const float* __restrict__ bf,
                            __half* __restrict__ Y) {
    int row = blockIdx.x;
    int tid = threadIdx.x;
    __shared__ float red[256];
    __shared__ float s_mu, s_inv;
    __shared__ float buf[kD];
    const float* x = X + (size_t)row * kD;
    float s = 0.0f;
    for (int i = tid; i < kD; i += 256) s += x[i];
    red[tid] = s; __syncthreads();
    for (int st = 128; st > 0; st >>= 1) { if (tid < st) red[tid] += red[tid + st]; __syncthreads(); }
    if (tid == 0) s_mu = red[0] / (float)kD;
    __syncthreads();
    float mu = s_mu;
    float v = 0.0f;
    for (int i = tid; i < kD; i += 256) { float d = x[i] - mu; v += d * d; }
    red[tid] = v; __syncthreads();
    for (int st = 128; st > 0; st >>= 1) { if (tid < st) red[tid] += red[tid + st]; __syncthreads(); }
    if (tid == 0) s_inv = 1.0f / sqrtf(red[0] / (float)kD + 1e-5f);
    __syncthreads();
    float inv = s_inv;
    for (int i = tid; i < kD; i += 256)
        buf[i] = (x[i] - mu) * inv * g2[i] + b2[i];
    __syncthreads();
    s = 0.0f;
    for (int i = tid; i < kD; i += 256) s += buf[i];
    red[tid] = s; __syncthreads();
    for (int st = 128; st > 0; st >>= 1) { if (tid < st) red[tid] += red[tid + st]; __syncthreads(); }
    if (tid == 0) s_mu = red[0] / (float)kD;
    __syncthreads();
    mu = s_mu;
    v = 0.0f;
    for (int i = tid; i < kD; i += 256) { float d = buf[i] - mu; v += d * d; }
    red[tid] = v; __syncthreads();
    for (int st = 128; st > 0; st >>= 1) { if (tid < st) red[tid] += red[tid + st]; __syncthreads(); }
    if (tid == 0) s_inv = 1.0f / sqrtf(red[0] / (float)kD + 1e-5f);
    __syncthreads();
    inv = s_inv;
    for (int i = tid; i < kD; i += 256)
        Y[(size_t)row * kD + i] = __float2half_rn((buf[i] - mu) * inv * gf[i] + bf[i]);
}

// ---------------- gate (half X) ----------------
__global__ void gate_kernel(const __half* __restrict__ X, const float* __restrict__ GW,
                            float* __restrict__ wdense, float* __restrict__ varbuf) {
    int t = blockIdx.x;
    int tid = threadIdx.x;
    __shared__ float red[128];
    __shared__ float logits[4];
    const __half* x = X + (size_t)t * kD;
    float acc[4] = {0.f, 0.f, 0.f, 0.f};
    for (int d = tid; d < kD; d += 128) {
        float xv = __half2float(x[d]);
        acc[0] += xv * GW[0 * kD + d];
        acc[1] += xv * GW[1 * kD + d];
        acc[2] += xv * GW[2 * kD + d];
        acc[3] += xv * GW[3 * kD + d];
    }
    for (int e = 0; e < 4; e++) {
        red[tid] = acc[e]; __syncthreads();
        for (int st = 64; st > 0; st >>= 1) { if (tid < st) red[tid] += red[tid + st]; __syncthreads(); }
        if (tid == 0) logits[e] = red[0];
        __syncthreads();
    }
    if (tid == 0) {
        float l[4] = {logits[0], logits[1], logits[2], logits[3]};
        float mx = fmaxf(fmaxf(l[0], l[1]), fmaxf(l[2], l[3]));
        float pe[4], ps = 0.f;
        for (int e = 0; e < 4; e++) { pe[e] = expf(l[e] - mx); ps += pe[e]; }
        float pr[4];
        for (int e = 0; e < 4; e++) pr[e] = pe[e] / ps;
        int a = 0;
        for (int e = 1; e < 4; e++) if (pr[e] > pr[a]) a = e;
        int b2 = -1;
        for (int e = 0; e < 4; e++) { if (e == a) continue; if (b2 < 0 || pr[e] > pr[b2]) b2 = e; }
        float wsum = pr[a] + pr[b2];
        float w[4] = {0.f, 0.f, 0.f, 0.f};
        w[a] = pr[a] / wsum; w[b2] = pr[b2] / wsum;
        for (int e = 0; e < 4; e++) wdense[t * 4 + e] = w[e];
        float mu = 0.25f * (l[0] + l[1] + l[2] + l[3]);
        float vv = 0.f;
        for (int e = 0; e < 4; e++) { float d = l[e] - mu; vv += d * d; }
        varbuf[t] = vv / 3.0f;
    }
}

__global__ void aux_kernel(const float* __restrict__ varbuf, float* __restrict__ out) {
    __shared__ float red[256];
    int tid = threadIdx.x;
    float s = 0.f;
    for (int i = tid; i < kS; i += 256) s += varbuf[i];
    red[tid] = s; __syncthreads();
    for (int st = 128; st > 0; st >>= 1) { if (tid < st) red[tid] += red[tid + st]; __syncthreads(); }
    if (tid == 0) out[0] = red[0] / (float)kS;
}

// ---------------- launch ----------------
extern "C" void kernel_launch(void* const* d_in, const int* in_sizes, int n_in,
                              void* d_out, int out_size) {
    const int*   tokens = (const int*)d_in[0];
    const float* emb    = (const float*)d_in[1];
    const float* wq     = (const float*)d_in[2];
    const float* wk     = (const float*)d_in[3];
    const float* wv     = (const float*)d_in[4];
    const float* wo     = (const float*)d_in[5];
    const float* ln1_g  = (const float*)d_in[6];
    const float* ln1_b  = (const float*)d_in[7];
    const float* gate_w = (const float*)d_in[8];
    const float* w1     = (const float*)d_in[9];
    const float* w2     = (const float*)d_in[10];
    const float* w3     = (const float*)d_in[11];
    const float* ln2_g  = (const float*)d_in[12];
    const float* ln2_b  = (const float*)d_in[13];
    const float* fin_g  = (const float*)d_in[14];
    const float* fin_b  = (const float*)d_in[15];
    const float* head_w = (const float*)d_in[16];
    float* out = (float*)d_out;

    __half *wqh, *wkh, *wvh, *woh, *w1h, *w3h, *w2h, *hdh;
    __half *x0h, *qkvh, *oh, *xn1h, *hah, *hbh, *x4h;
    float *part, *x1, *x2, *wdense, *varbuf;
    cudaGetSymbolAddress((void**)&wqh, g_wqh);
    cudaGetSymbolAddress((void**)&wkh, g_wkh);
    cudaGetSymbolAddress((void**)&wvh, g_wvh);
    cudaGetSymbolAddress((void**)&woh, g_woh);
    cudaGetSymbolAddress((void**)&w1h, g_w1h);
    cudaGetSymbolAddress((void**)&w3h, g_w3h);
    cudaGetSymbolAddress((void**)&w2h, g_w2h);
    cudaGetSymbolAddress((void**)&hdh, g_hdh);
    cudaGetSymbolAddress((void**)&x0h,  g_x0h);
    cudaGetSymbolAddress((void**)&qkvh, g_qkvh);
    cudaGetSymbolAddress((void**)&oh,   g_oh);
    cudaGetSymbolAddress((void**)&xn1h, g_xn1h);
    cudaGetSymbolAddress((void**)&hah,  g_hah);
    cudaGetSymbolAddress((void**)&hbh,  g_hbh);
    cudaGetSymbolAddress((void**)&x4h,  g_x4h);
    cudaGetSymbolAddress((void**)&part, g_part);
    cudaGetSymbolAddress((void**)&x1,  g_x1);
    cudaGetSymbolAddress((void**)&x2,  g_x2);
    cudaGetSymbolAddress((void**)&wdense, g_wdense);
    cudaGetSymbolAddress((void**)&varbuf, g_var);

    const int SD = kS * kD;
    const int KFD = kF * kD;

    cudaFuncSetAttribute(gemm_h, cudaFuncAttributeMaxDynamicSharedMemorySize, GEMM_SMEM);

    // ---- convert weights to fp16 ----
    {
        int nDD = kD * kD / 4;
        cvt_h<<<(nDD + 255) / 256, 256>>>(wq, wqh, nDD);
        cvt_h<<<(nDD + 255) / 256, 256>>>(wk, wkh, nDD);
        cvt_h<<<(nDD + 255) / 256, 256>>>(wv, wvh, nDD);
        cvt_h<<<(nDD + 255) / 256, 256>>>(wo, woh, nDD);
        int nFD = kNE * KFD / 4;
        cvt_h<<<(nFD + 255) / 256, 256>>>(w1, w1h, nFD);
        cvt_h<<<(nFD + 255) / 256, 256>>>(w3, w3h, nFD);
        cvt_h<<<(nFD + 255) / 256, 256>>>(w2, w2h, nFD);
        int nHD = kVOC * kD / 4;
        cvt_h<<<(nHD + 255) / 256, 256>>>(head_w, hdh, nHD);
    }

    // embed
    embed_kernel<<<SD / 256, 256>>>(tokens, emb, x0h);

    // QKV (split-K=2 -> fp32 partials -> half qkv)
    gemm_h<<<dim3(kS / 128, 48, 2), 256, GEMM_SMEM>>>(
        x0h, wqh, wkh, wvh, nullptr, part, nullptr,
        3 * kD, kD / BKH, kD, kD, 3 * kD,
        11, -1, kD / BKH / 2, (long long)kS * 3 * kD,
        0, nullptr, 0, nullptr);
    reduce_k<<<(kS * 3 * kD + 255) / 256, 256>>>(part, nullptr, nullptr, qkvh, kS * 3 * kD);

    // rope
    rope_kernel<<<(2 * kS * kH * 32) / 256, 256>>>(qkvh);

    // attention
    int attn_smem = (3 * 64 * 68 + 64) * (int)sizeof(float);
    cudaFuncSetAttribute(attn_kernel, cudaFuncAttributeMaxDynamicSharedMemorySize, attn_smem);
    attn_kernel<<<dim3(kS / 64, kH), 256, attn_smem>>>(qkvh, oh);

    // wo (split-K=2) -> partials; reduce with x0 residual -> x1 fp32
    gemm_h<<<dim3(kS / 128, kD / 128, 2), 256, GEMM_SMEM>>>(
        oh, woh, nullptr, nullptr, nullptr, part, nullptr,
        kD, kD / BKH, kD, kD, kD,
        30, -1, kD / BKH / 2, (long long)SD,
        0, nullptr, 0, nullptr);
    reduce_k<<<(SD + 255) / 256, 256>>>(part, x0h, x1, nullptr, SD);

    // ln1 -> half xn1
    ln_kernel<<<kS, 256>>>(x1, ln1_g, ln1_b, xn1h);

    // gate + aux
    gate_kernel<<<kS, 128>>>(xn1h, gate_w, wdense, varbuf);
    aux_kernel<<<1, 256>>>(varbuf, out + (size_t)out_size - 1);

    // MoE: all-expert w1 -> ha (half)
    gemm_h<<<dim3(kS / 128, 256), 256, GEMM_SMEM>>>(
        xn1h, w1h, w1h + (size_t)KFD, w1h + 2 * (size_t)KFD, w1h + 3 * (size_t)KFD,
        nullptr, hah, kNE * kF, kD / BKH, kD, kD, kNE * kF,
        13, -1, kD / BKH, 0,
        0, nullptr, 0, nullptr);

    // all-expert w3 with fused gate+silu epilogue -> hb (half)
    gemm_h<<<dim3(kS / 128, 256), 256, GEMM_SMEM>>>(
        xn1h, w3h, w3h + (size_t)KFD, w3h + 2 * (size_t)KFD, w3h + 3 * (size_t)KFD,
        nullptr, hbh, kNE * kF, kD / BKH, kD, kD, kNE * kF,
        13, -1, kD / BKH, 0,
        2, hah, kNE * kF, wdense);

    // fused 4-expert w2, K=32768, split-K=2 -> partials; reduce + xn1 residual -> x2
    gemm_h<<<dim3(kS / 128, kD / 128, 2), 256, GEMM_SMEM>>>(
        hbh, w2h, w2h + (size_t)KFD, w2h + 2 * (size_t)KFD, w2h + 3 * (size_t)KFD,
        part, nullptr, kD, (kNE * kF) / BKH, kNE * kF, kF, kD,
        30, 7, (kNE * kF) / BKH / 2, (long long)SD,
        0, nullptr, 0, nullptr);
    reduce_k<<<(SD + 255) / 256, 256>>>(part, xn1h, x2, nullptr, SD);

    // ln2 + final ln -> half x4
    ln2x_kernel<<<kS, 256>>>(x2, ln2_g, ln2_b, fin_g, fin_b, x4h);

    // LM head -> fp32 logits
    gemm_h<<<dim3(kS / 128, (kVOC + 127) / 128), 256, GEMM_SMEM>>>(
        x4h, hdh, nullptr, nullptr, nullptr, out, nullptr,
        kVOC, kD / BKH, kD, kD, kVOC,
        30, -1, kD / BKH, 0,
        0, nullptr, 0, nullptr);
}